// round 5
// baseline (speedup 1.0000x reference)
#include <cuda_runtime.h>
#include <math.h>

#define NB 2
#define NC 256
#define NH 64
#define HW 4096
#define HW2 (HW * HW)

// ---------------- scratch (static __device__ globals; no allocations) ----------------
__device__ float g_part[8 * NB * HW];          // partial channel sum-of-squares
__device__ float g_inv[NB * HW];               // 1 / max(||x||, 1e-12)
__device__ float g_L[NB * HW2];                // masked scaled logits (134 MB)
__device__ float g_mp[NB * 2 * HW];            // partial row maxes (per N-half)
__device__ float g_m[NB * HW];                 // row max
__device__ float g_Zr[NB * HW];                // 1 / row sum exp
__device__ float g_S[NB * HW];                 // row sum of x_c, then reciprocal

// ---------------- K1a: partial sum of squares over channel chunks ----------------
__global__ __launch_bounds__(256) void norm_part_kernel(const float* __restrict__ x) {
    int p  = blockIdx.x * 256 + threadIdx.x;   // 0..8191 (b*4096 + pixel)
    int cb = blockIdx.y;                        // 0..7 channel chunk
    int b  = p >> 12;
    int pi = p & (HW - 1);
    const float* xb = x + (size_t)b * NC * HW + (size_t)cb * 32 * HW + pi;
    float s = 0.f;
#pragma unroll
    for (int c = 0; c < 32; ++c) {
        float v = xb[(size_t)c * HW];
        s += v * v;
    }
    g_part[cb * (NB * HW) + p] = s;
}

// ---------------- K1b: finalize inverse norms ----------------
__global__ __launch_bounds__(256) void norm_fin_kernel() {
    int p = blockIdx.x * 256 + threadIdx.x;
    float s = 0.f;
#pragma unroll
    for (int cb = 0; cb < 8; ++cb) s += g_part[cb * (NB * HW) + p];
    g_inv[p] = 1.0f / fmaxf(sqrtf(s), 1e-12f);
}

// ---------------- K2: GEMM (L = alpha * mask * aff) + partial row max ----------------
// grid: (64 row-tiles, 2 N-halves, 2 batches), block 256 (16x16), 4x4 per thread.
__global__ __launch_bounds__(256) void gemm_kernel(const float* __restrict__ x,
                                                   const float* __restrict__ alpha_p) {
    __shared__ float As[16][64];
    __shared__ float Bs[16][64];
    __shared__ float gt[64];
    __shared__ float smx[64][17];

    int rt = blockIdx.x, nh = blockIdx.y, b = blockIdx.z;
    int row0 = rt * 64;
    int tid = threadIdx.x;
    int tx = tid & 15, ty = tid >> 4;
    float alpha = *alpha_p;

    if (tid < 64) {
        float d = (float)tid;
        gt[tid] = expf(-d * d * (1.0f / (2.0f * 3.2f * 3.2f)));
    }

    const float* A = x + (size_t)b * NC * HW;
    int lr = tid >> 4;          // smem load row   0..15
    int lc = (tid & 15) << 2;   // smem load col*4 0..60

    float rmax[4] = {-1e30f, -1e30f, -1e30f, -1e30f};
    float invA[4];
#pragma unroll
    for (int i = 0; i < 4; ++i) invA[i] = g_inv[b * HW + row0 + (ty << 2) + i];

    for (int nt = 0; nt < 32; ++nt) {
        int col0 = nh * 2048 + nt * 64;
        float acc[4][4];
#pragma unroll
        for (int i = 0; i < 4; ++i)
#pragma unroll
            for (int j = 0; j < 4; ++j) acc[i][j] = 0.f;

        for (int k0 = 0; k0 < NC; k0 += 16) {
            __syncthreads();
            *(float4*)&As[lr][lc] = *(const float4*)&A[(size_t)(k0 + lr) * HW + row0 + lc];
            *(float4*)&Bs[lr][lc] = *(const float4*)&A[(size_t)(k0 + lr) * HW + col0 + lc];
            __syncthreads();
#pragma unroll
            for (int kk = 0; kk < 16; ++kk) {
                float4 av = *(float4*)&As[kk][ty << 2];
                float4 bv = *(float4*)&Bs[kk][tx << 2];
                acc[0][0] += av.x * bv.x; acc[0][1] += av.x * bv.y;
                acc[0][2] += av.x * bv.z; acc[0][3] += av.x * bv.w;
                acc[1][0] += av.y * bv.x; acc[1][1] += av.y * bv.y;
                acc[1][2] += av.y * bv.z; acc[1][3] += av.y * bv.w;
                acc[2][0] += av.z * bv.x; acc[2][1] += av.z * bv.y;
                acc[2][2] += av.z * bv.z; acc[2][3] += av.z * bv.w;
                acc[3][0] += av.w * bv.x; acc[3][1] += av.w * bv.y;
                acc[3][2] += av.w * bv.z; acc[3][3] += av.w * bv.w;
            }
        }

        float invB[4];
#pragma unroll
        for (int j = 0; j < 4; ++j) invB[j] = g_inv[b * HW + col0 + (tx << 2) + j];

#pragma unroll
        for (int i = 0; i < 4; ++i) {
            int s = row0 + (ty << 2) + i;
            int sr = s >> 6, sc = s & 63;
            float4 o;
            float* op = &o.x;
#pragma unroll
            for (int j = 0; j < 4; ++j) {
                int t = col0 + (tx << 2) + j;
                int tr = t >> 6, tc = t & 63;
                int dr = sr - tr; dr = dr < 0 ? -dr : dr;
                int dc = sc - tc; dc = dc < 0 ? -dc : dc;
                float msk = 1.0f - gt[dr] * gt[dc];
                float L = acc[i][j] * invA[i] * invB[j] * msk * alpha;
                op[j] = L;
                rmax[i] = fmaxf(rmax[i], L);
            }
            *(float4*)&g_L[(size_t)b * HW2 + (size_t)s * HW + col0 + (tx << 2)] = o;
        }
    }

    __syncthreads();
#pragma unroll
    for (int i = 0; i < 4; ++i) smx[(ty << 2) + i][tx] = rmax[i];
    __syncthreads();
    if (tid < 64) {
        float m = smx[tid][0];
#pragma unroll
        for (int j = 1; j < 16; ++j) m = fmaxf(m, smx[tid][j]);
        g_mp[(b * 2 + nh) * HW + row0 + tid] = m;
    }
}

// ---------------- K3: row max combine + Z = sum exp(L - m) ----------------
__global__ __launch_bounds__(256) void rowz_kernel() {
    int r = blockIdx.x;                         // 0..8191
    int b = r >> 12, s = r & (HW - 1);
    float m = fmaxf(g_mp[(b * 2 + 0) * HW + s], g_mp[(b * 2 + 1) * HW + s]);
    const float* Lr = g_L + (size_t)r * HW;
    float sum = 0.f;
    int tid = threadIdx.x;
    for (int t = tid << 2; t < HW; t += 1024) {
        float4 L4 = *(const float4*)&Lr[t];
        sum += __expf(L4.x - m) + __expf(L4.y - m) + __expf(L4.z - m) + __expf(L4.w - m);
    }
    __shared__ float sd[256];
    sd[tid] = sum;
    __syncthreads();
    for (int st = 128; st > 0; st >>= 1) {
        if (tid < st) sd[tid] += sd[tid + st];
        __syncthreads();
    }
    if (tid == 0) { g_m[r] = m; g_Zr[r] = 1.0f / sd[0]; }
}

// ---------------- top-3 helper ----------------
__device__ __forceinline__ void top3_insert(float v, float& a, float& b, float& c) {
    if (v > c) {
        if (v > a)      { c = b; b = a; a = v; }
        else if (v > b) { c = b; b = v; }
        else            { c = v; }
    }
}

// ---------------- K4: x_c, row sum S, top-3, write x_c to output ----------------
__global__ __launch_bounds__(256) void xc_kernel(float* __restrict__ out_val,
                                                 float* __restrict__ out_soft) {
    int r = blockIdx.x;
    int b = r >> 12, s = r & (HW - 1);
    float ms = g_m[r], zs = g_Zr[r];
    const float* mB = g_m + (b << 12);
    const float* zB = g_Zr + (b << 12);
    const float* Lr = g_L + (size_t)r * HW;
    float* orow = out_soft + (size_t)r * HW;

    float S = 0.f, t0 = -1.f, t1 = -1.f, t2 = -1.f;
    int tid = threadIdx.x;
    for (int t = tid << 2; t < HW; t += 1024) {
        float4 L4 = *(const float4*)&Lr[t];
        float4 m4 = *(const float4*)&mB[t];
        float4 z4 = *(const float4*)&zB[t];
        float4 v;
        v.x = __expf(2.f * L4.x - ms - m4.x) * (zs * z4.x);
        v.y = __expf(2.f * L4.y - ms - m4.y) * (zs * z4.y);
        v.z = __expf(2.f * L4.z - ms - m4.z) * (zs * z4.z);
        v.w = __expf(2.f * L4.w - ms - m4.w) * (zs * z4.w);
        *(float4*)&orow[t] = v;
        S += (v.x + v.y) + (v.z + v.w);
        top3_insert(v.x, t0, t1, t2);
        top3_insert(v.y, t0, t1, t2);
        top3_insert(v.z, t0, t1, t2);
        top3_insert(v.w, t0, t1, t2);
    }

    __shared__ float sS[256], sa[256], sb[256], sc[256];
    sS[tid] = S; sa[tid] = t0; sb[tid] = t1; sc[tid] = t2;
    __syncthreads();
    for (int st = 128; st > 0; st >>= 1) {
        if (tid < st) {
            sS[tid] += sS[tid + st];
            float a0 = sa[tid + st], a1 = sb[tid + st], a2 = sc[tid + st];
            float b0 = sa[tid], b1 = sb[tid], b2 = sc[tid];
            top3_insert(a0, b0, b1, b2);
            top3_insert(a1, b0, b1, b2);
            top3_insert(a2, b0, b1, b2);
            sa[tid] = b0; sb[tid] = b1; sc[tid] = b2;
        }
        __syncthreads();
    }
    if (tid == 0) {
        g_S[r] = sS[0];
        // val[b][k][t] with t = this row (top-3 over source axis == top-3 of row by symmetry)
        out_val[(b * 3 + 0) * HW + s] = sa[0];
        out_val[(b * 3 + 1) * HW + s] = sb[0];
        out_val[(b * 3 + 2) * HW + s] = sc[0];
    }
}

// ---------------- K4b: S -> 1/(S + 1e-8) ----------------
__global__ __launch_bounds__(256) void srecip_kernel() {
    int i = blockIdx.x * 256 + threadIdx.x;
    g_S[i] = 1.0f / (g_S[i] + 1e-8f);
}

// ---------------- K5: in-place column scaling of x_soft ----------------
__global__ __launch_bounds__(256) void scale_kernel(float* __restrict__ soft) {
    size_t i4 = ((size_t)blockIdx.x * 256 + threadIdx.x) << 2;
    int t = (int)(i4 & (size_t)(HW - 1));
    int b = (int)(i4 >> 24);  // HW*HW = 2^24
    float4 v = *(float4*)&soft[i4];
    float4 sv = *(const float4*)&g_S[(b << 12) + t];
    v.x *= sv.x; v.y *= sv.y; v.z *= sv.z; v.w *= sv.w;
    *(float4*)&soft[i4] = v;
}

// ---------------- launch ----------------
extern "C" void kernel_launch(void* const* d_in, const int* in_sizes, int n_in,
                              void* d_out, int out_size) {
    const float* x = (const float*)d_in[0];
    const float* alpha = (const float*)d_in[1];
    float* out = (float*)d_out;
    float* out_val = out;                       // (2,3,64,64) = 24576
    float* out_soft = out + NB * 3 * HW;        // (2,4096,64,64)

    norm_part_kernel<<<dim3(32, 8), 256>>>(x);
    norm_fin_kernel<<<32, 256>>>();
    gemm_kernel<<<dim3(64, 2, NB), 256>>>(x, alpha);
    rowz_kernel<<<NB * HW, 256>>>();
    xc_kernel<<<NB * HW, 256>>>(out_val, out_soft);
    srecip_kernel<<<32, 256>>>();
    scale_kernel<<<(NB * HW2 / 4) / 256, 256>>>(out_soft);
}

// round 8
// speedup vs baseline: 2.4086x; 2.4086x over previous
#include <cuda_runtime.h>
#include <cuda_bf16.h>
#include <math.h>
#include <stdint.h>

#define NB 2
#define NC 256
#define HW 4096
#define HW2 (HW * HW)

// ---------------- scratch (static __device__ globals; no allocations) ----------------
__device__ float g_part[8 * NB * HW];
__device__ float g_inv[NB * HW];
__device__ float g_L[NB * HW2];                 // masked scaled logits (134 MB)
__device__ float g_mp[NB * 32 * HW];            // per (row, col-tile) local max
__device__ float g_sp[NB * 32 * HW];            // per (row, col-tile) local sumexp
__device__ float g_m[NB * HW];                  // row max
__device__ float g_zs[NB * HW];                 // 1 / row sum exp
__device__ float g_E[NB * HW];                  // exp(-m_t) * z_t
__device__ float g_S[NB * HW];                  // row sum of x_c
__device__ float g_W[NB * HW];                  // e_t / (S_t + 1e-8)
__device__ __nv_bfloat16 g_xh[(size_t)NB * HW * NC];   // normalized, [pixel][chan], hi
__device__ __nv_bfloat16 g_xl[(size_t)NB * HW * NC];   // residual lo

// ---------------- ptx helpers (plain sm_103-legal: ldmatrix / mma.sync / cp.async) ----
static __device__ __forceinline__ uint32_t s2u(const void* p) {
    uint32_t a;
    asm("{ .reg .u64 t; cvta.to.shared.u64 t, %1; cvt.u32.u64 %0, t; }" : "=r"(a) : "l"(p));
    return a;
}
static __device__ __forceinline__ void cpa16(uint32_t dst, const void* src) {
    asm volatile("cp.async.cg.shared.global [%0], [%1], 16;" :: "r"(dst), "l"(src));
}
static __device__ __forceinline__ void ldm4(uint32_t* r, uint32_t a) {
    asm volatile("ldmatrix.sync.aligned.m8n8.x4.shared.b16 {%0,%1,%2,%3}, [%4];"
        : "=r"(r[0]), "=r"(r[1]), "=r"(r[2]), "=r"(r[3]) : "r"(a));
}
static __device__ __forceinline__ void mma16816(float* c, const uint32_t* a,
                                                uint32_t b0, uint32_t b1) {
    asm volatile("mma.sync.aligned.m16n8k16.row.col.f32.bf16.bf16.f32 "
        "{%0,%1,%2,%3}, {%4,%5,%6,%7}, {%8,%9}, {%0,%1,%2,%3};"
        : "+f"(c[0]), "+f"(c[1]), "+f"(c[2]), "+f"(c[3])
        : "r"(a[0]), "r"(a[1]), "r"(a[2]), "r"(a[3]), "r"(b0), "r"(b1));
}

// ---------------- K1a: partial sum of squares ----------------
__global__ __launch_bounds__(256) void norm_part_kernel(const float* __restrict__ x) {
    int p  = blockIdx.x * 256 + threadIdx.x;
    int cb = blockIdx.y;
    int b  = p >> 12;
    int pi = p & (HW - 1);
    const float* xb = x + (size_t)b * NC * HW + (size_t)cb * 32 * HW + pi;
    float s = 0.f;
#pragma unroll
    for (int c = 0; c < 32; ++c) { float v = xb[(size_t)c * HW]; s += v * v; }
    g_part[cb * (NB * HW) + p] = s;
}

// ---------------- K1b: finalize inverse norms ----------------
__global__ __launch_bounds__(256) void norm_fin_kernel() {
    int p = blockIdx.x * 256 + threadIdx.x;
    float s = 0.f;
#pragma unroll
    for (int cb = 0; cb < 8; ++cb) s += g_part[cb * (NB * HW) + p];
    g_inv[p] = 1.0f / fmaxf(sqrtf(s), 1e-12f);
}

// ---------------- K1c: normalize + split bf16 + transpose -> [p][c] ----------------
__global__ __launch_bounds__(256) void prep_kernel(const float* __restrict__ x) {
    __shared__ float sh[32][33];
    int p0 = blockIdx.x * 32, c0 = blockIdx.y * 32, b = blockIdx.z;
    int tx = threadIdx.x & 31, ty = threadIdx.x >> 5;
    const float* xb = x + (size_t)b * NC * HW;
#pragma unroll
    for (int i = 0; i < 4; ++i) {
        int c = c0 + ty + i * 8, p = p0 + tx;
        sh[ty + i * 8][tx] = xb[(size_t)c * HW + p] * g_inv[b * HW + p];
    }
    __syncthreads();
#pragma unroll
    for (int i = 0; i < 4; ++i) {
        int p = p0 + ty + i * 8, c = c0 + tx;
        float v = sh[tx][ty + i * 8];
        __nv_bfloat16 h = __float2bfloat16(v);
        float lo = v - __bfloat162float(h);
        size_t o = (size_t)(b * HW + p) * NC + c;
        g_xh[o] = h;
        g_xl[o] = __float2bfloat16(lo);
    }
}

// ---------------- K2: mma.sync bf16 GEMM (3-product split) + fused epilogue ----------
// grid (32 col-tiles, 32 row-tiles, 2 batches), 256 threads = 8 warps (4 m x 2 n).
// dynamic smem: 2 stages x 4 buffers(Ah,Al,Bh,Bl) x 128 rows x 144 B = 147456 B
#define AST 144
#define BUF 18432
#define STAGE 73728

__global__ __launch_bounds__(256) void gemm_mma_kernel(const float* __restrict__ alpha_p) {
    extern __shared__ char dsm[];
    __shared__ float s_gt[64];
    __shared__ float s_ms[128][2];
    __shared__ float s_ss[128][2];

    int tid = threadIdx.x, lane = tid & 31, wid = tid >> 5;
    int ct = blockIdx.x, rt = blockIdx.y, b = blockIdx.z;
    int col0 = ct * 128, row0 = rt * 128;
    int warp_m = wid & 3, warp_n = wid >> 2;

    if (tid < 64) {
        float d = (float)tid;
        s_gt[tid] = expf(-d * d * (1.0f / (2.0f * 3.2f * 3.2f)));
    }

    const char* xh = (const char*)(g_xh + (size_t)b * HW * NC);
    const char* xl = (const char*)(g_xl + (size_t)b * HW * NC);
    uint32_t smb = s2u(dsm);

    float acc[2][8][4];
#pragma unroll
    for (int mt = 0; mt < 2; ++mt)
#pragma unroll
        for (int nt = 0; nt < 8; ++nt)
#pragma unroll
            for (int q = 0; q < 4; ++q) acc[mt][nt][q] = 0.f;

    // ---- prologue: load chunk 0 into stage 0 ----
    {
        uint32_t sb = smb;
#pragma unroll
        for (int i = 0; i < 4; ++i) {
            int idx = i * 256 + tid;
            int r = idx >> 3, cc = idx & 7;
            uint32_t so = (uint32_t)(r * AST + cc * 16);
            size_t goA = (size_t)(row0 + r) * 512 + cc * 16;
            size_t goB = (size_t)(col0 + r) * 512 + cc * 16;
            cpa16(sb + 0 * BUF + so, xh + goA);
            cpa16(sb + 1 * BUF + so, xl + goA);
            cpa16(sb + 2 * BUF + so, xh + goB);
            cpa16(sb + 3 * BUF + so, xl + goB);
        }
        asm volatile("cp.async.commit_group;" ::: "memory");
    }

    int grp = lane >> 3, rr8 = lane & 7;
    int aro = ((grp & 1) << 3) + rr8;                 // A: grp1/3 -> row+8
    int ako = (grp & 2) << 3;                          // A: grp2/3 -> k+16B
    int bro = ((grp >> 1) << 3) + rr8;                 // B: grp2/3 -> n-row+8
    int bko = (grp & 1) << 4;                          // B: grp1/3 -> k+16B

    for (int ch = 0; ch < 4; ++ch) {
        asm volatile("cp.async.wait_group 0;" ::: "memory");
        __syncthreads();
        if (ch < 3) {
            uint32_t sb = smb + ((ch + 1) & 1) * STAGE;
            int kofB = (ch + 1) * 128;
#pragma unroll
            for (int i = 0; i < 4; ++i) {
                int idx = i * 256 + tid;
                int r = idx >> 3, cc = idx & 7;
                uint32_t so = (uint32_t)(r * AST + cc * 16);
                size_t goA = (size_t)(row0 + r) * 512 + kofB + cc * 16;
                size_t goB = (size_t)(col0 + r) * 512 + kofB + cc * 16;
                cpa16(sb + 0 * BUF + so, xh + goA);
                cpa16(sb + 1 * BUF + so, xl + goA);
                cpa16(sb + 2 * BUF + so, xh + goB);
                cpa16(sb + 3 * BUF + so, xl + goB);
            }
            asm volatile("cp.async.commit_group;" ::: "memory");
        }
        uint32_t sb = smb + (ch & 1) * STAGE;
#pragma unroll
        for (int ks = 0; ks < 4; ++ks) {
            uint32_t ah[2][4], al[2][4];
#pragma unroll
            for (int mt = 0; mt < 2; ++mt) {
                int ar = warp_m * 32 + mt * 16 + aro;
                uint32_t ao = (uint32_t)(ar * AST + ks * 32 + ako);
                ldm4(ah[mt], sb + 0 * BUF + ao);
                ldm4(al[mt], sb + 1 * BUF + ao);
            }
#pragma unroll
            for (int p = 0; p < 4; ++p) {
                int br = warp_n * 64 + p * 16 + bro;
                uint32_t bo = (uint32_t)(br * AST + ks * 32 + bko);
                uint32_t bh_[4], bl_[4];
                ldm4(bh_, sb + 2 * BUF + bo);
                ldm4(bl_, sb + 3 * BUF + bo);
#pragma unroll
                for (int mt = 0; mt < 2; ++mt) {
                    mma16816(acc[mt][2 * p],     ah[mt], bh_[0], bh_[1]);   // hi*hi
                    mma16816(acc[mt][2 * p + 1], ah[mt], bh_[2], bh_[3]);
                    mma16816(acc[mt][2 * p],     al[mt], bh_[0], bh_[1]);   // lo*hi
                    mma16816(acc[mt][2 * p + 1], al[mt], bh_[2], bh_[3]);
                    mma16816(acc[mt][2 * p],     ah[mt], bl_[0], bl_[1]);   // hi*lo
                    mma16816(acc[mt][2 * p + 1], ah[mt], bl_[2], bl_[3]);
                }
            }
        }
    }
    __syncthreads();

    // ---- epilogue: mask*alpha (operands already normalized!), store L,
    //      per-(row, col-tile) online max + sumexp ----
    float alpha = *alpha_p;
    int g = lane >> 2, c4 = lane & 3;
    float* Lout = g_L + (size_t)b * HW2;

#pragma unroll
    for (int mt = 0; mt < 2; ++mt)
#pragma unroll
        for (int half = 0; half < 2; ++half) {
            int rloc = warp_m * 32 + mt * 16 + half * 8 + g;
            int srow = row0 + rloc;
            int sr = srow >> 6, sc = srow & 63;
            float vmax = -1e30f;
#pragma unroll
            for (int nt = 0; nt < 8; ++nt) {
                float2 Lp;
#pragma unroll
                for (int h = 0; h < 2; ++h) {
                    int tcol = col0 + warp_n * 64 + nt * 8 + (c4 << 1) + h;
                    int tr = tcol >> 6, tc = tcol & 63;
                    int dr = sr - tr; dr = dr < 0 ? -dr : dr;
                    int dc = sc - tc; dc = dc < 0 ? -dc : dc;
                    float L = acc[mt][nt][half * 2 + h] * alpha
                              * (1.0f - s_gt[dr] * s_gt[dc]);
                    acc[mt][nt][half * 2 + h] = L;
                    ((float*)&Lp)[h] = L;
                    vmax = fmaxf(vmax, L);
                }
                *(float2*)&Lout[(size_t)srow * HW + col0 + warp_n * 64 + nt * 8 + (c4 << 1)] = Lp;
            }
            float ssum = 0.f;
#pragma unroll
            for (int nt = 0; nt < 8; ++nt) {
                ssum += __expf(acc[mt][nt][half * 2]     - vmax);
                ssum += __expf(acc[mt][nt][half * 2 + 1] - vmax);
            }
            // combine across the 4 lanes sharing this row
#pragma unroll
            for (int m2 = 1; m2 <= 2; m2 <<= 1) {
                float om = __shfl_xor_sync(0xFFFFFFFFu, vmax, m2);
                float os = __shfl_xor_sync(0xFFFFFFFFu, ssum, m2);
                float nm = fmaxf(vmax, om);
                ssum = ssum * __expf(vmax - nm) + os * __expf(om - nm);
                vmax = nm;
            }
            if (c4 == 0) { s_ms[rloc][warp_n] = vmax; s_ss[rloc][warp_n] = ssum; }
        }
    __syncthreads();
    if (tid < 128) {
        float m0 = s_ms[tid][0], m1 = s_ms[tid][1];
        float m = fmaxf(m0, m1);
        float s = s_ss[tid][0] * __expf(m0 - m) + s_ss[tid][1] * __expf(m1 - m);
        g_mp[((size_t)b * 32 + ct) * HW + row0 + tid] = m;
        g_sp[((size_t)b * 32 + ct) * HW + row0 + tid] = s;
    }
}

// ---------------- K3: combine per-tile partials -> m, 1/Z, e ----------------
__global__ __launch_bounds__(256) void rowcomb_kernel() {
    int r = blockIdx.x * 256 + threadIdx.x;      // 0..8191
    int b = r >> 12, rr = r & (HW - 1);
    float m = -1e30f;
#pragma unroll
    for (int ctile = 0; ctile < 32; ++ctile)
        m = fmaxf(m, g_mp[((size_t)b * 32 + ctile) * HW + rr]);
    float s = 0.f;
#pragma unroll
    for (int ctile = 0; ctile < 32; ++ctile)
        s += g_sp[((size_t)b * 32 + ctile) * HW + rr]
             * __expf(g_mp[((size_t)b * 32 + ctile) * HW + rr] - m);
    float z = 1.0f / s;
    g_m[r] = m;
    g_zs[r] = z;
    g_E[r] = __expf(-m) * z;
}

// ---------------- top-3 helper ----------------
__device__ __forceinline__ void top3_insert(float v, float& a, float& b, float& c) {
    if (v > c) {
        if (v > a)      { c = b; b = a; a = v; }
        else if (v > b) { c = b; b = v; }
        else            { c = v; }
    }
}

// ---------------- K4: stats pass (S + top3), read-only over L ----------------
__global__ __launch_bounds__(256) void stats_kernel(float* __restrict__ out_val) {
    __shared__ float sE[HW];
    __shared__ float sS[256], sa[256], sb2[256], sc2[256];
    int r = blockIdx.x, b = r >> 12, sidx = r & (HW - 1);
    int tid = threadIdx.x;
    for (int i = tid << 2; i < HW; i += 1024)
        *(float4*)&sE[i] = *(const float4*)&g_E[(b << 12) + i];
    float ms = g_m[r], zs = g_zs[r];
    const float* Lr = g_L + (size_t)r * HW;
    __syncthreads();

    float S = 0.f, t0 = -1.f, t1 = -1.f, t2 = -1.f;
    for (int t = tid << 2; t < HW; t += 1024) {
        float4 L4 = *(const float4*)&Lr[t];
        float4 e4 = *(const float4*)&sE[t];
        float vx = __expf(2.f * L4.x - ms) * zs * e4.x;
        float vy = __expf(2.f * L4.y - ms) * zs * e4.y;
        float vz = __expf(2.f * L4.z - ms) * zs * e4.z;
        float vw = __expf(2.f * L4.w - ms) * zs * e4.w;
        S += (vx + vy) + (vz + vw);
        top3_insert(vx, t0, t1, t2);
        top3_insert(vy, t0, t1, t2);
        top3_insert(vz, t0, t1, t2);
        top3_insert(vw, t0, t1, t2);
    }
    sS[tid] = S; sa[tid] = t0; sb2[tid] = t1; sc2[tid] = t2;
    __syncthreads();
    for (int st = 128; st > 0; st >>= 1) {
        if (tid < st) {
            sS[tid] += sS[tid + st];
            float a0 = sa[tid + st], a1 = sb2[tid + st], a2 = sc2[tid + st];
            float b0 = sa[tid], b1 = sb2[tid], b2 = sc2[tid];
            top3_insert(a0, b0, b1, b2);
            top3_insert(a1, b0, b1, b2);
            top3_insert(a2, b0, b1, b2);
            sa[tid] = b0; sb2[tid] = b1; sc2[tid] = b2;
        }
        __syncthreads();
    }
    if (tid == 0) {
        g_S[r] = sS[0];
        out_val[(b * 3 + 0) * HW + sidx] = sa[0];
        out_val[(b * 3 + 1) * HW + sidx] = sb2[0];
        out_val[(b * 3 + 2) * HW + sidx] = sc2[0];
    }
}

// ---------------- K4b: w = e / (S + 1e-8) ----------------
__global__ __launch_bounds__(256) void srecip_kernel() {
    int i = blockIdx.x * 256 + threadIdx.x;
    g_W[i] = g_E[i] / (g_S[i] + 1e-8f);
}

// ---------------- K5: write scaled x_soft directly ----------------
__global__ __launch_bounds__(256) void write_kernel(float* __restrict__ out_soft) {
    __shared__ float sW[HW];
    int r = blockIdx.x, b = r >> 12;
    int tid = threadIdx.x;
    for (int i = tid << 2; i < HW; i += 1024)
        *(float4*)&sW[i] = *(const float4*)&g_W[(b << 12) + i];
    float ms = g_m[r], zs = g_zs[r];
    const float* Lr = g_L + (size_t)r * HW;
    float* Or = out_soft + (size_t)r * HW;
    __syncthreads();
    for (int t = tid << 2; t < HW; t += 1024) {
        float4 L4 = *(const float4*)&Lr[t];
        float4 w4 = *(const float4*)&sW[t];
        float4 v;
        v.x = __expf(2.f * L4.x - ms) * zs * w4.x;
        v.y = __expf(2.f * L4.y - ms) * zs * w4.y;
        v.z = __expf(2.f * L4.z - ms) * zs * w4.z;
        v.w = __expf(2.f * L4.w - ms) * zs * w4.w;
        *(float4*)&Or[t] = v;
    }
}

// ---------------- launch ----------------
extern "C" void kernel_launch(void* const* d_in, const int* in_sizes, int n_in,
                              void* d_out, int out_size) {
    const float* x = (const float*)d_in[0];
    const float* alpha = (const float*)d_in[1];
    float* out = (float*)d_out;
    float* out_val = out;                    // (2,3,64,64)
    float* out_soft = out + NB * 3 * HW;     // (2,4096,64,64)

    cudaFuncSetAttribute(gemm_mma_kernel,
                         cudaFuncAttributeMaxDynamicSharedMemorySize, 2 * STAGE);

    norm_part_kernel<<<dim3(32, 8), 256>>>(x);
    norm_fin_kernel<<<32, 256>>>();
    prep_kernel<<<dim3(128, 8, NB), 256>>>(x);
    gemm_mma_kernel<<<dim3(32, 32, NB), 256, 2 * STAGE>>>(alpha);
    rowcomb_kernel<<<32, 256>>>();
    stats_kernel<<<NB * HW, 256>>>(out_val);
    srecip_kernel<<<32, 256>>>();
    write_kernel<<<NB * HW, 256>>>(out_soft);
}

// round 9
// speedup vs baseline: 3.0788x; 1.2782x over previous
#include <cuda_runtime.h>
#include <cuda_bf16.h>
#include <math.h>
#include <stdint.h>

#define NB 2
#define NC 256
#define HW 4096
#define HW2 (HW * HW)

// ---------------- scratch (static __device__ globals; no allocations) ----------------
__device__ float g_part[8 * NB * HW];
__device__ float g_inv[NB * HW];
__device__ float g_L[NB * HW2];                 // masked scaled logits (134 MB)
__device__ float g_mp[NB * 32 * HW];            // per (row, col-tile) local max
__device__ float g_sp[NB * 32 * HW];            // per (row, col-tile) local sumexp
__device__ float g_m[NB * HW];                  // row max
__device__ float g_zs[NB * HW];                 // 1 / row sum exp
__device__ float g_E[NB * HW];                  // exp(-m_t) * z_t
__device__ float g_S[NB * HW];                  // row sum of x_c
__device__ float g_W[NB * HW];                  // e_t / (S_t + 1e-8)
__device__ __nv_bfloat16 g_xh[(size_t)NB * HW * NC];   // normalized, [pixel][chan], hi
__device__ __nv_bfloat16 g_xl[(size_t)NB * HW * NC];   // residual lo

// ---------------- ptx helpers ----------------
static __device__ __forceinline__ uint32_t s2u(const void* p) {
    uint32_t a;
    asm("{ .reg .u64 t; cvta.to.shared.u64 t, %1; cvt.u32.u64 %0, t; }" : "=r"(a) : "l"(p));
    return a;
}
static __device__ __forceinline__ void cpa16(uint32_t dst, const void* src) {
    asm volatile("cp.async.cg.shared.global [%0], [%1], 16;" :: "r"(dst), "l"(src));
}
static __device__ __forceinline__ void ldm4(uint32_t* r, uint32_t a) {
    asm volatile("ldmatrix.sync.aligned.m8n8.x4.shared.b16 {%0,%1,%2,%3}, [%4];"
        : "=r"(r[0]), "=r"(r[1]), "=r"(r[2]), "=r"(r[3]) : "r"(a));
}
static __device__ __forceinline__ void mma16816(float* c, const uint32_t* a,
                                                uint32_t b0, uint32_t b1) {
    asm volatile("mma.sync.aligned.m16n8k16.row.col.f32.bf16.bf16.f32 "
        "{%0,%1,%2,%3}, {%4,%5,%6,%7}, {%8,%9}, {%0,%1,%2,%3};"
        : "+f"(c[0]), "+f"(c[1]), "+f"(c[2]), "+f"(c[3])
        : "r"(a[0]), "r"(a[1]), "r"(a[2]), "r"(a[3]), "r"(b0), "r"(b1));
}

// ---------------- K1a: partial sum of squares ----------------
__global__ __launch_bounds__(256) void norm_part_kernel(const float* __restrict__ x) {
    int p  = blockIdx.x * 256 + threadIdx.x;
    int cb = blockIdx.y;
    int b  = p >> 12;
    int pi = p & (HW - 1);
    const float* xb = x + (size_t)b * NC * HW + (size_t)cb * 32 * HW + pi;
    float s = 0.f;
#pragma unroll
    for (int c = 0; c < 32; ++c) { float v = xb[(size_t)c * HW]; s += v * v; }
    g_part[cb * (NB * HW) + p] = s;
}

// ---------------- K1b: finalize inverse norms ----------------
__global__ __launch_bounds__(256) void norm_fin_kernel() {
    int p = blockIdx.x * 256 + threadIdx.x;
    float s = 0.f;
#pragma unroll
    for (int cb = 0; cb < 8; ++cb) s += g_part[cb * (NB * HW) + p];
    g_inv[p] = 1.0f / fmaxf(sqrtf(s), 1e-12f);
}

// ---------------- K1c: normalize + split bf16 + transpose -> [p][c] ----------------
__global__ __launch_bounds__(256) void prep_kernel(const float* __restrict__ x) {
    __shared__ float sh[32][33];
    int p0 = blockIdx.x * 32, c0 = blockIdx.y * 32, b = blockIdx.z;
    int tx = threadIdx.x & 31, ty = threadIdx.x >> 5;
    const float* xb = x + (size_t)b * NC * HW;
#pragma unroll
    for (int i = 0; i < 4; ++i) {
        int c = c0 + ty + i * 8, p = p0 + tx;
        sh[ty + i * 8][tx] = xb[(size_t)c * HW + p] * g_inv[b * HW + p];
    }
    __syncthreads();
#pragma unroll
    for (int i = 0; i < 4; ++i) {
        int p = p0 + ty + i * 8, c = c0 + tx;
        float v = sh[tx][ty + i * 8];
        __nv_bfloat16 h = __float2bfloat16(v);
        float lo = v - __bfloat162float(h);
        size_t o = (size_t)(b * HW + p) * NC + c;
        g_xh[o] = h;
        g_xl[o] = __float2bfloat16(lo);
    }
}

// ---------------- K2: symmetric mma.sync bf16 GEMM + fused epilogue ----------
// grid (528 upper-tri tiles, NB batches), 256 threads = 8 warps (4 m x 2 n).
#define AST 144
#define BUF 18432
#define STAGE 73728

__global__ __launch_bounds__(256) void gemm_mma_kernel(const float* __restrict__ alpha_p) {
    extern __shared__ char dsm[];
    __shared__ float s_gt[64];
    __shared__ float s_ms[128][2];
    __shared__ float s_ss[128][2];
    __shared__ float s_cms[128][4];
    __shared__ float s_css[128][4];

    int tid = threadIdx.x, lane = tid & 31, wid = tid >> 5;
    int b = blockIdx.y;

    // decode upper-triangular tile (rt <= ct)
    int u = 527 - (int)blockIdx.x;
    int i_ = (int)((sqrtf(8.0f * u + 1.0f) - 1.0f) * 0.5f);
    while (i_ * (i_ + 1) / 2 > u) --i_;
    while ((i_ + 1) * (i_ + 2) / 2 <= u) ++i_;
    int j_ = u - i_ * (i_ + 1) / 2;
    int rt = 31 - i_, ct = 31 - j_;
    int row0 = rt * 128, col0 = ct * 128;
    bool mirror = (ct > rt);

    int warp_m = wid & 3, warp_n = wid >> 2;

    if (tid < 64) {
        float d = (float)tid;
        s_gt[tid] = expf(-d * d * (1.0f / (2.0f * 3.2f * 3.2f)));
    }

    const char* xh = (const char*)(g_xh + (size_t)b * HW * NC);
    const char* xl = (const char*)(g_xl + (size_t)b * HW * NC);
    uint32_t smb = s2u(dsm);

    float acc[2][8][4];
#pragma unroll
    for (int mt = 0; mt < 2; ++mt)
#pragma unroll
        for (int nt = 0; nt < 8; ++nt)
#pragma unroll
            for (int q = 0; q < 4; ++q) acc[mt][nt][q] = 0.f;

    // ---- prologue: load chunk 0 into stage 0 ----
    {
        uint32_t sb = smb;
#pragma unroll
        for (int i = 0; i < 4; ++i) {
            int idx = i * 256 + tid;
            int r = idx >> 3, cc = idx & 7;
            uint32_t so = (uint32_t)(r * AST + cc * 16);
            size_t goA = (size_t)(row0 + r) * 512 + cc * 16;
            size_t goB = (size_t)(col0 + r) * 512 + cc * 16;
            cpa16(sb + 0 * BUF + so, xh + goA);
            cpa16(sb + 1 * BUF + so, xl + goA);
            cpa16(sb + 2 * BUF + so, xh + goB);
            cpa16(sb + 3 * BUF + so, xl + goB);
        }
        asm volatile("cp.async.commit_group;" ::: "memory");
    }

    int grp = lane >> 3, rr8 = lane & 7;
    int aro = ((grp & 1) << 3) + rr8;
    int ako = (grp & 2) << 3;
    int bro = ((grp >> 1) << 3) + rr8;
    int bko = (grp & 1) << 4;

    for (int ch = 0; ch < 4; ++ch) {
        asm volatile("cp.async.wait_group 0;" ::: "memory");
        __syncthreads();
        if (ch < 3) {
            uint32_t sb = smb + ((ch + 1) & 1) * STAGE;
            int kofB = (ch + 1) * 128;
#pragma unroll
            for (int i = 0; i < 4; ++i) {
                int idx = i * 256 + tid;
                int r = idx >> 3, cc = idx & 7;
                uint32_t so = (uint32_t)(r * AST + cc * 16);
                size_t goA = (size_t)(row0 + r) * 512 + kofB + cc * 16;
                size_t goB = (size_t)(col0 + r) * 512 + kofB + cc * 16;
                cpa16(sb + 0 * BUF + so, xh + goA);
                cpa16(sb + 1 * BUF + so, xl + goA);
                cpa16(sb + 2 * BUF + so, xh + goB);
                cpa16(sb + 3 * BUF + so, xl + goB);
            }
            asm volatile("cp.async.commit_group;" ::: "memory");
        }
        uint32_t sb = smb + (ch & 1) * STAGE;
#pragma unroll
        for (int ks = 0; ks < 4; ++ks) {
            uint32_t ah[2][4], al[2][4];
#pragma unroll
            for (int mt = 0; mt < 2; ++mt) {
                int ar = warp_m * 32 + mt * 16 + aro;
                uint32_t ao = (uint32_t)(ar * AST + ks * 32 + ako);
                ldm4(ah[mt], sb + 0 * BUF + ao);
                ldm4(al[mt], sb + 1 * BUF + ao);
            }
#pragma unroll
            for (int p = 0; p < 4; ++p) {
                int br = warp_n * 64 + p * 16 + bro;
                uint32_t bo = (uint32_t)(br * AST + ks * 32 + bko);
                uint32_t bh_[4], bl_[4];
                ldm4(bh_, sb + 2 * BUF + bo);
                ldm4(bl_, sb + 3 * BUF + bo);
                // interleaved: same-acc HMMAs are >=4 apart
                mma16816(acc[0][2 * p],     ah[0], bh_[0], bh_[1]);
                mma16816(acc[0][2 * p + 1], ah[0], bh_[2], bh_[3]);
                mma16816(acc[1][2 * p],     ah[1], bh_[0], bh_[1]);
                mma16816(acc[1][2 * p + 1], ah[1], bh_[2], bh_[3]);
                mma16816(acc[0][2 * p],     al[0], bh_[0], bh_[1]);
                mma16816(acc[0][2 * p + 1], al[0], bh_[2], bh_[3]);
                mma16816(acc[1][2 * p],     al[1], bh_[0], bh_[1]);
                mma16816(acc[1][2 * p + 1], al[1], bh_[2], bh_[3]);
                mma16816(acc[0][2 * p],     ah[0], bl_[0], bl_[1]);
                mma16816(acc[0][2 * p + 1], ah[0], bl_[2], bl_[3]);
                mma16816(acc[1][2 * p],     ah[1], bl_[0], bl_[1]);
                mma16816(acc[1][2 * p + 1], ah[1], bl_[2], bl_[3]);
            }
        }
    }
    __syncthreads();   // stage buffers dead; s_t may alias dsm

    // ---- epilogue ----
    float alpha = *alpha_p;
    int g = lane >> 2, c4 = lane & 3;
    float* Lout = g_L + (size_t)b * HW2;
    float* s_t = (float*)dsm;          // [128][129] transpose staging

    // 1) mask*alpha, direct store, stage transpose
#pragma unroll
    for (int mt = 0; mt < 2; ++mt)
#pragma unroll
        for (int half = 0; half < 2; ++half) {
            int rloc = warp_m * 32 + mt * 16 + half * 8 + g;
            int srow = row0 + rloc;
            int sr = srow >> 6, sc = srow & 63;
#pragma unroll
            for (int nt = 0; nt < 8; ++nt) {
                int cbase = warp_n * 64 + nt * 8 + (c4 << 1);
                float2 Lp;
#pragma unroll
                for (int h = 0; h < 2; ++h) {
                    int tcol = col0 + cbase + h;
                    int tr = tcol >> 6, tc = tcol & 63;
                    int dr = sr - tr; dr = dr < 0 ? -dr : dr;
                    int dc = sc - tc; dc = dc < 0 ? -dc : dc;
                    float L = acc[mt][nt][half * 2 + h] * alpha
                              * (1.0f - s_gt[dr] * s_gt[dc]);
                    acc[mt][nt][half * 2 + h] = L;
                    ((float*)&Lp)[h] = L;
                }
                *(float2*)&Lout[(size_t)srow * HW + col0 + cbase] = Lp;
                if (mirror) {
                    s_t[rloc * 129 + cbase]     = Lp.x;
                    s_t[rloc * 129 + cbase + 1] = Lp.y;
                }
            }
        }

    // 2) row stats
#pragma unroll
    for (int mt = 0; mt < 2; ++mt)
#pragma unroll
        for (int half = 0; half < 2; ++half) {
            int rloc = warp_m * 32 + mt * 16 + half * 8 + g;
            float vmax = -1e30f;
#pragma unroll
            for (int nt = 0; nt < 8; ++nt) {
                vmax = fmaxf(vmax, acc[mt][nt][half * 2]);
                vmax = fmaxf(vmax, acc[mt][nt][half * 2 + 1]);
            }
            float ssum = 0.f;
#pragma unroll
            for (int nt = 0; nt < 8; ++nt) {
                ssum += __expf(acc[mt][nt][half * 2]     - vmax);
                ssum += __expf(acc[mt][nt][half * 2 + 1] - vmax);
            }
#pragma unroll
            for (int m2 = 1; m2 <= 2; m2 <<= 1) {
                float om = __shfl_xor_sync(0xFFFFFFFFu, vmax, m2);
                float os = __shfl_xor_sync(0xFFFFFFFFu, ssum, m2);
                float nm = fmaxf(vmax, om);
                ssum = ssum * __expf(vmax - nm) + os * __expf(om - nm);
                vmax = nm;
            }
            if (c4 == 0) { s_ms[rloc][warp_n] = vmax; s_ss[rloc][warp_n] = ssum; }
        }

    // 3) column stats (mirror tiles only) — overwrite acc[*][nt][0..1]
    if (mirror) {
#pragma unroll
        for (int nt = 0; nt < 8; ++nt)
#pragma unroll
            for (int h = 0; h < 2; ++h) {
                float v0 = acc[0][nt][h], v1 = acc[0][nt][2 + h];
                float v2 = acc[1][nt][h], v3 = acc[1][nt][2 + h];
                float cm = fmaxf(fmaxf(v0, v1), fmaxf(v2, v3));
                float cs = __expf(v0 - cm) + __expf(v1 - cm)
                         + __expf(v2 - cm) + __expf(v3 - cm);
#pragma unroll
                for (int m2 = 4; m2 <= 16; m2 <<= 1) {
                    float om = __shfl_xor_sync(0xFFFFFFFFu, cm, m2);
                    float os = __shfl_xor_sync(0xFFFFFFFFu, cs, m2);
                    float nm = fmaxf(cm, om);
                    cs = cs * __expf(cm - nm) + os * __expf(om - nm);
                    cm = nm;
                }
                acc[0][nt][h] = cm;
                acc[1][nt][h] = cs;
            }
        if (g == 0) {
#pragma unroll
            for (int nt = 0; nt < 8; ++nt)
#pragma unroll
                for (int h = 0; h < 2; ++h) {
                    int cloc = warp_n * 64 + nt * 8 + (c4 << 1) + h;
                    s_cms[cloc][warp_m] = acc[0][nt][h];
                    s_css[cloc][warp_m] = acc[1][nt][h];
                }
        }
    }
    __syncthreads();

    if (tid < 128) {
        float m0 = s_ms[tid][0], m1 = s_ms[tid][1];
        float m = fmaxf(m0, m1);
        float s = s_ss[tid][0] * __expf(m0 - m) + s_ss[tid][1] * __expf(m1 - m);
        g_mp[((size_t)b * 32 + ct) * HW + row0 + tid] = m;
        g_sp[((size_t)b * 32 + ct) * HW + row0 + tid] = s;
    }
    if (mirror && tid < 128) {
        float m = fmaxf(fmaxf(s_cms[tid][0], s_cms[tid][1]),
                        fmaxf(s_cms[tid][2], s_cms[tid][3]));
        float s = s_css[tid][0] * __expf(s_cms[tid][0] - m)
                + s_css[tid][1] * __expf(s_cms[tid][1] - m)
                + s_css[tid][2] * __expf(s_cms[tid][2] - m)
                + s_css[tid][3] * __expf(s_cms[tid][3] - m);
        g_mp[((size_t)b * 32 + rt) * HW + col0 + tid] = m;
        g_sp[((size_t)b * 32 + rt) * HW + col0 + tid] = s;
    }

    // 4) mirrored L store (transposed tile), coalesced
    if (mirror) {
        for (int i = tid; i < 8192; i += 256) {
            int trow = i >> 6;               // 0..127: row of mirror tile (= col of orig)
            int tc2 = (i & 63) << 1;         // 0..126: col of mirror tile (= row of orig)
            float2 v;
            v.x = s_t[tc2 * 129 + trow];
            v.y = s_t[(tc2 + 1) * 129 + trow];
            *(float2*)&Lout[(size_t)(col0 + trow) * HW + row0 + tc2] = v;
        }
    }
}

// ---------------- K3: combine per-tile partials -> m, 1/Z, e ----------------
__global__ __launch_bounds__(256) void rowcomb_kernel() {
    int r = blockIdx.x * 256 + threadIdx.x;
    int b = r >> 12, rr = r & (HW - 1);
    float m = -1e30f;
#pragma unroll
    for (int ctile = 0; ctile < 32; ++ctile)
        m = fmaxf(m, g_mp[((size_t)b * 32 + ctile) * HW + rr]);
    float s = 0.f;
#pragma unroll
    for (int ctile = 0; ctile < 32; ++ctile)
        s += g_sp[((size_t)b * 32 + ctile) * HW + rr]
             * __expf(g_mp[((size_t)b * 32 + ctile) * HW + rr] - m);
    float z = 1.0f / s;
    g_m[r] = m;
    g_zs[r] = z;
    g_E[r] = __expf(-m) * z;
}

// ---------------- top-3 helper ----------------
__device__ __forceinline__ void top3_insert(float v, float& a, float& b, float& c) {
    if (v > c) {
        if (v > a)      { c = b; b = a; a = v; }
        else if (v > b) { c = b; b = v; }
        else            { c = v; }
    }
}

// ---------------- K4: stats pass (S + top3), read-only over L ----------------
__global__ __launch_bounds__(256) void stats_kernel(float* __restrict__ out_val) {
    __shared__ float sE[HW];
    __shared__ float sS[256], sa[256], sb2[256], sc2[256];
    int r = blockIdx.x, b = r >> 12, sidx = r & (HW - 1);
    int tid = threadIdx.x;
    for (int i = tid << 2; i < HW; i += 1024)
        *(float4*)&sE[i] = *(const float4*)&g_E[(b << 12) + i];
    float ms = g_m[r], zs = g_zs[r];
    const float* Lr = g_L + (size_t)r * HW;
    __syncthreads();

    float S = 0.f, t0 = -1.f, t1 = -1.f, t2 = -1.f;
    for (int t = tid << 2; t < HW; t += 1024) {
        float4 L4 = *(const float4*)&Lr[t];
        float4 e4 = *(const float4*)&sE[t];
        float vx = __expf(2.f * L4.x - ms) * zs * e4.x;
        float vy = __expf(2.f * L4.y - ms) * zs * e4.y;
        float vz = __expf(2.f * L4.z - ms) * zs * e4.z;
        float vw = __expf(2.f * L4.w - ms) * zs * e4.w;
        S += (vx + vy) + (vz + vw);
        top3_insert(vx, t0, t1, t2);
        top3_insert(vy, t0, t1, t2);
        top3_insert(vz, t0, t1, t2);
        top3_insert(vw, t0, t1, t2);
    }
    sS[tid] = S; sa[tid] = t0; sb2[tid] = t1; sc2[tid] = t2;
    __syncthreads();
    for (int st = 128; st > 0; st >>= 1) {
        if (tid < st) {
            sS[tid] += sS[tid + st];
            float a0 = sa[tid + st], a1 = sb2[tid + st], a2 = sc2[tid + st];
            float b0 = sa[tid], b1 = sb2[tid], b2 = sc2[tid];
            top3_insert(a0, b0, b1, b2);
            top3_insert(a1, b0, b1, b2);
            top3_insert(a2, b0, b1, b2);
            sa[tid] = b0; sb2[tid] = b1; sc2[tid] = b2;
        }
        __syncthreads();
    }
    if (tid == 0) {
        g_S[r] = sS[0];
        out_val[(b * 3 + 0) * HW + sidx] = sa[0];
        out_val[(b * 3 + 1) * HW + sidx] = sb2[0];
        out_val[(b * 3 + 2) * HW + sidx] = sc2[0];
    }
}

// ---------------- K4b: w = e / (S + 1e-8) ----------------
__global__ __launch_bounds__(256) void srecip_kernel() {
    int i = blockIdx.x * 256 + threadIdx.x;
    g_W[i] = g_E[i] / (g_S[i] + 1e-8f);
}

// ---------------- K5: write scaled x_soft directly ----------------
__global__ __launch_bounds__(256) void write_kernel(float* __restrict__ out_soft) {
    __shared__ float sW[HW];
    int r = blockIdx.x, b = r >> 12;
    int tid = threadIdx.x;
    for (int i = tid << 2; i < HW; i += 1024)
        *(float4*)&sW[i] = *(const float4*)&g_W[(b << 12) + i];
    float ms = g_m[r], zs = g_zs[r];
    const float* Lr = g_L + (size_t)r * HW;
    float* Or = out_soft + (size_t)r * HW;
    __syncthreads();
    for (int t = tid << 2; t < HW; t += 1024) {
        float4 L4 = *(const float4*)&Lr[t];
        float4 w4 = *(const float4*)&sW[t];
        float4 v;
        v.x = __expf(2.f * L4.x - ms) * zs * w4.x;
        v.y = __expf(2.f * L4.y - ms) * zs * w4.y;
        v.z = __expf(2.f * L4.z - ms) * zs * w4.z;
        v.w = __expf(2.f * L4.w - ms) * zs * w4.w;
        *(float4*)&Or[t] = v;
    }
}

// ---------------- launch ----------------
extern "C" void kernel_launch(void* const* d_in, const int* in_sizes, int n_in,
                              void* d_out, int out_size) {
    const float* x = (const float*)d_in[0];
    const float* alpha = (const float*)d_in[1];
    float* out = (float*)d_out;
    float* out_val = out;                    // (2,3,64,64)
    float* out_soft = out + NB * 3 * HW;     // (2,4096,64,64)

    cudaFuncSetAttribute(gemm_mma_kernel,
                         cudaFuncAttributeMaxDynamicSharedMemorySize, 2 * STAGE);

    norm_part_kernel<<<dim3(32, 8), 256>>>(x);
    norm_fin_kernel<<<32, 256>>>();
    prep_kernel<<<dim3(128, 8, NB), 256>>>(x);
    gemm_mma_kernel<<<dim3(528, NB), 256, 2 * STAGE>>>(alpha);
    rowcomb_kernel<<<32, 256>>>();
    stats_kernel<<<NB * HW, 256>>>(out_val);
    srecip_kernel<<<32, 256>>>();
    write_kernel<<<NB * HW, 256>>>(out_soft);
}

// round 10
// speedup vs baseline: 3.3208x; 1.0786x over previous
#include <cuda_runtime.h>
#include <cuda_bf16.h>
#include <math.h>
#include <stdint.h>

#define NB 2
#define NC 256
#define HW 4096
#define HW2 (HW * HW)

// ---------------- scratch (static __device__ globals; no allocations) ----------------
__device__ float g_part[8 * NB * HW];
__device__ float g_inv[NB * HW];
__device__ float g_L[NB * HW2];                 // masked scaled logits (134 MB)
__device__ float g_mp[NB * 32 * HW];            // per (row, col-tile) local max
__device__ float g_sp[NB * 32 * HW];            // per (row, col-tile) local sumexp
__device__ float g_m[NB * HW];                  // row max
__device__ float g_zs[NB * HW];                 // 1 / row sum exp
__device__ float g_E[NB * HW];                  // exp(-m_t) * z_t
__device__ float g_S[NB * HW];                  // row sum of x_c
__device__ float g_W[NB * HW];                  // e_t / (S_t + 1e-8)
__device__ __nv_bfloat16 g_xh[(size_t)NB * HW * NC];   // normalized, [pixel][chan], hi
__device__ __nv_bfloat16 g_xl[(size_t)NB * HW * NC];   // residual lo

// ---------------- ptx helpers ----------------
static __device__ __forceinline__ uint32_t s2u(const void* p) {
    uint32_t a;
    asm("{ .reg .u64 t; cvta.to.shared.u64 t, %1; cvt.u32.u64 %0, t; }" : "=r"(a) : "l"(p));
    return a;
}
static __device__ __forceinline__ void cpa16(uint32_t dst, const void* src) {
    asm volatile("cp.async.cg.shared.global [%0], [%1], 16;" :: "r"(dst), "l"(src));
}
static __device__ __forceinline__ void ldm4(uint32_t* r, uint32_t a) {
    asm volatile("ldmatrix.sync.aligned.m8n8.x4.shared.b16 {%0,%1,%2,%3}, [%4];"
        : "=r"(r[0]), "=r"(r[1]), "=r"(r[2]), "=r"(r[3]) : "r"(a));
}
static __device__ __forceinline__ void mma16816(float* c, const uint32_t* a,
                                                uint32_t b0, uint32_t b1) {
    asm volatile("mma.sync.aligned.m16n8k16.row.col.f32.bf16.bf16.f32 "
        "{%0,%1,%2,%3}, {%4,%5,%6,%7}, {%8,%9}, {%0,%1,%2,%3};"
        : "+f"(c[0]), "+f"(c[1]), "+f"(c[2]), "+f"(c[3])
        : "r"(a[0]), "r"(a[1]), "r"(a[2]), "r"(a[3]), "r"(b0), "r"(b1));
}

// ---------------- K1a: partial sum of squares ----------------
__global__ __launch_bounds__(256) void norm_part_kernel(const float* __restrict__ x) {
    int p  = blockIdx.x * 256 + threadIdx.x;
    int cb = blockIdx.y;
    int b  = p >> 12;
    int pi = p & (HW - 1);
    const float* xb = x + (size_t)b * NC * HW + (size_t)cb * 32 * HW + pi;
    float s = 0.f;
#pragma unroll
    for (int c = 0; c < 32; ++c) { float v = xb[(size_t)c * HW]; s += v * v; }
    g_part[cb * (NB * HW) + p] = s;
}

// ---------------- K1b: finalize inverse norms ----------------
__global__ __launch_bounds__(256) void norm_fin_kernel() {
    int p = blockIdx.x * 256 + threadIdx.x;
    float s = 0.f;
#pragma unroll
    for (int cb = 0; cb < 8; ++cb) s += g_part[cb * (NB * HW) + p];
    g_inv[p] = 1.0f / fmaxf(sqrtf(s), 1e-12f);
}

// ---------------- K1c: normalize + split bf16 + transpose -> [p][c] ----------------
__global__ __launch_bounds__(256) void prep_kernel(const float* __restrict__ x) {
    __shared__ float sh[32][33];
    int p0 = blockIdx.x * 32, c0 = blockIdx.y * 32, b = blockIdx.z;
    int tx = threadIdx.x & 31, ty = threadIdx.x >> 5;
    const float* xb = x + (size_t)b * NC * HW;
#pragma unroll
    for (int i = 0; i < 4; ++i) {
        int c = c0 + ty + i * 8, p = p0 + tx;
        sh[ty + i * 8][tx] = xb[(size_t)c * HW + p] * g_inv[b * HW + p];
    }
    __syncthreads();
#pragma unroll
    for (int i = 0; i < 4; ++i) {
        int p = p0 + ty + i * 8, c = c0 + tx;
        float v = sh[tx][ty + i * 8];
        __nv_bfloat16 h = __float2bfloat16(v);
        float lo = v - __bfloat162float(h);
        size_t o = (size_t)(b * HW + p) * NC + c;
        g_xh[o] = h;
        g_xl[o] = __float2bfloat16(lo);
    }
}

// ---------------- K2: symmetric mma.sync bf16 GEMM + fused epilogue ----------
// grid (528 upper-tri tiles, NB batches), 256 threads = 8 warps (4 m x 2 n).
// 64B K-chunks (8 of them), stride 80 -> 2 stages x 4 bufs x 128 x 80 = 81920 B dsm
// => 2 CTAs/SM (occupancy fix).
#define AST 80
#define BUF (128 * AST)
#define STAGE (4 * BUF)
#define NCH 8

__global__ __launch_bounds__(256, 2) void gemm_mma_kernel(const float* __restrict__ alpha_p) {
    extern __shared__ char dsm[];
    __shared__ float s_gt[64];
    __shared__ float s_ms[128][2];
    __shared__ float s_ss[128][2];
    __shared__ float s_cms[128][4];
    __shared__ float s_css[128][4];

    int tid = threadIdx.x, lane = tid & 31, wid = tid >> 5;
    int b = blockIdx.y;

    // decode upper-triangular tile (rt <= ct)
    int u = 527 - (int)blockIdx.x;
    int i_ = (int)((sqrtf(8.0f * u + 1.0f) - 1.0f) * 0.5f);
    while (i_ * (i_ + 1) / 2 > u) --i_;
    while ((i_ + 1) * (i_ + 2) / 2 <= u) ++i_;
    int j_ = u - i_ * (i_ + 1) / 2;
    int rt = 31 - i_, ct = 31 - j_;
    int row0 = rt * 128, col0 = ct * 128;
    bool mirror = (ct > rt);

    int warp_m = wid & 3, warp_n = wid >> 2;

    if (tid < 64) {
        float d = (float)tid;
        s_gt[tid] = expf(-d * d * (1.0f / (2.0f * 3.2f * 3.2f)));
    }

    const char* xh = (const char*)(g_xh + (size_t)b * HW * NC);
    const char* xl = (const char*)(g_xl + (size_t)b * HW * NC);
    uint32_t smb = s2u(dsm);

    float acc[2][8][4];
#pragma unroll
    for (int mt = 0; mt < 2; ++mt)
#pragma unroll
        for (int nt = 0; nt < 8; ++nt)
#pragma unroll
            for (int q = 0; q < 4; ++q) acc[mt][nt][q] = 0.f;

    // ---- prologue: load chunk 0 into stage 0 ----
#pragma unroll
    for (int i = 0; i < 8; ++i) {
        int buf = i >> 1;
        int rem = ((i & 1) << 8) + tid;
        int r = rem >> 2, cc = rem & 3;
        uint32_t so = (uint32_t)(buf * BUF + r * AST + cc * 16);
        size_t go = (size_t)(((buf & 2) ? col0 : row0) + r) * 512 + cc * 16;
        cpa16(smb + so, ((buf & 1) ? xl : xh) + go);
    }
    asm volatile("cp.async.commit_group;" ::: "memory");

    int grp = lane >> 3, rr8 = lane & 7;
    int aro = ((grp & 1) << 3) + rr8;
    int ako = (grp & 2) << 3;
    int bro = ((grp >> 1) << 3) + rr8;
    int bko = (grp & 1) << 4;

    for (int ch = 0; ch < NCH; ++ch) {
        asm volatile("cp.async.wait_group 0;" ::: "memory");
        __syncthreads();
        if (ch < NCH - 1) {
            uint32_t sb = smb + ((ch + 1) & 1) * STAGE;
            int kof = (ch + 1) * 64;
#pragma unroll
            for (int i = 0; i < 8; ++i) {
                int buf = i >> 1;
                int rem = ((i & 1) << 8) + tid;
                int r = rem >> 2, cc = rem & 3;
                uint32_t so = (uint32_t)(buf * BUF + r * AST + cc * 16);
                size_t go = (size_t)(((buf & 2) ? col0 : row0) + r) * 512 + kof + cc * 16;
                cpa16(sb + so, ((buf & 1) ? xl : xh) + go);
            }
            asm volatile("cp.async.commit_group;" ::: "memory");
        }
        uint32_t sb = smb + (ch & 1) * STAGE;
#pragma unroll
        for (int ks = 0; ks < 2; ++ks) {
            uint32_t ah[2][4], al[2][4];
#pragma unroll
            for (int mt = 0; mt < 2; ++mt) {
                int ar = warp_m * 32 + mt * 16 + aro;
                uint32_t ao = (uint32_t)(ar * AST + ks * 32 + ako);
                ldm4(ah[mt], sb + 0 * BUF + ao);
                ldm4(al[mt], sb + 1 * BUF + ao);
            }
#pragma unroll
            for (int p = 0; p < 4; ++p) {
                int br = warp_n * 64 + p * 16 + bro;
                uint32_t bo = (uint32_t)(br * AST + ks * 32 + bko);
                uint32_t bh_[4], bl_[4];
                ldm4(bh_, sb + 2 * BUF + bo);
                ldm4(bl_, sb + 3 * BUF + bo);
                // interleaved: same-acc HMMAs are >=4 apart
                mma16816(acc[0][2 * p],     ah[0], bh_[0], bh_[1]);
                mma16816(acc[0][2 * p + 1], ah[0], bh_[2], bh_[3]);
                mma16816(acc[1][2 * p],     ah[1], bh_[0], bh_[1]);
                mma16816(acc[1][2 * p + 1], ah[1], bh_[2], bh_[3]);
                mma16816(acc[0][2 * p],     al[0], bh_[0], bh_[1]);
                mma16816(acc[0][2 * p + 1], al[0], bh_[2], bh_[3]);
                mma16816(acc[1][2 * p],     al[1], bh_[0], bh_[1]);
                mma16816(acc[1][2 * p + 1], al[1], bh_[2], bh_[3]);
                mma16816(acc[0][2 * p],     ah[0], bl_[0], bl_[1]);
                mma16816(acc[0][2 * p + 1], ah[0], bl_[2], bl_[3]);
                mma16816(acc[1][2 * p],     ah[1], bl_[0], bl_[1]);
                mma16816(acc[1][2 * p + 1], ah[1], bl_[2], bl_[3]);
            }
        }
    }
    __syncthreads();   // stage buffers dead; s_t may alias dsm

    // ---- epilogue ----
    float alpha = *alpha_p;
    int g = lane >> 2, c4 = lane & 3;
    float* Lout = g_L + (size_t)b * HW2;
    float* s_t = (float*)dsm;          // [128][129] transpose staging (66 KB <= 80 KB)

    // 1) mask*alpha, direct store, stage transpose
#pragma unroll
    for (int mt = 0; mt < 2; ++mt)
#pragma unroll
        for (int half = 0; half < 2; ++half) {
            int rloc = warp_m * 32 + mt * 16 + half * 8 + g;
            int srow = row0 + rloc;
            int sr = srow >> 6, sc = srow & 63;
#pragma unroll
            for (int nt = 0; nt < 8; ++nt) {
                int cbase = warp_n * 64 + nt * 8 + (c4 << 1);
                float2 Lp;
#pragma unroll
                for (int h = 0; h < 2; ++h) {
                    int tcol = col0 + cbase + h;
                    int tr = tcol >> 6, tc = tcol & 63;
                    int dr = sr - tr; dr = dr < 0 ? -dr : dr;
                    int dc = sc - tc; dc = dc < 0 ? -dc : dc;
                    float L = acc[mt][nt][half * 2 + h] * alpha
                              * (1.0f - s_gt[dr] * s_gt[dc]);
                    acc[mt][nt][half * 2 + h] = L;
                    ((float*)&Lp)[h] = L;
                }
                *(float2*)&Lout[(size_t)srow * HW + col0 + cbase] = Lp;
                if (mirror) {
                    s_t[rloc * 129 + cbase]     = Lp.x;
                    s_t[rloc * 129 + cbase + 1] = Lp.y;
                }
            }
        }

    // 2) row stats
#pragma unroll
    for (int mt = 0; mt < 2; ++mt)
#pragma unroll
        for (int half = 0; half < 2; ++half) {
            int rloc = warp_m * 32 + mt * 16 + half * 8 + g;
            float vmax = -1e30f;
#pragma unroll
            for (int nt = 0; nt < 8; ++nt) {
                vmax = fmaxf(vmax, acc[mt][nt][half * 2]);
                vmax = fmaxf(vmax, acc[mt][nt][half * 2 + 1]);
            }
            float ssum = 0.f;
#pragma unroll
            for (int nt = 0; nt < 8; ++nt) {
                ssum += __expf(acc[mt][nt][half * 2]     - vmax);
                ssum += __expf(acc[mt][nt][half * 2 + 1] - vmax);
            }
#pragma unroll
            for (int m2 = 1; m2 <= 2; m2 <<= 1) {
                float om = __shfl_xor_sync(0xFFFFFFFFu, vmax, m2);
                float os = __shfl_xor_sync(0xFFFFFFFFu, ssum, m2);
                float nm = fmaxf(vmax, om);
                ssum = ssum * __expf(vmax - nm) + os * __expf(om - nm);
                vmax = nm;
            }
            if (c4 == 0) { s_ms[rloc][warp_n] = vmax; s_ss[rloc][warp_n] = ssum; }
        }

    // 3) column stats (mirror tiles only) — overwrite acc[*][nt][0..1]
    if (mirror) {
#pragma unroll
        for (int nt = 0; nt < 8; ++nt)
#pragma unroll
            for (int h = 0; h < 2; ++h) {
                float v0 = acc[0][nt][h], v1 = acc[0][nt][2 + h];
                float v2 = acc[1][nt][h], v3 = acc[1][nt][2 + h];
                float cm = fmaxf(fmaxf(v0, v1), fmaxf(v2, v3));
                float cs = __expf(v0 - cm) + __expf(v1 - cm)
                         + __expf(v2 - cm) + __expf(v3 - cm);
#pragma unroll
                for (int m2 = 4; m2 <= 16; m2 <<= 1) {
                    float om = __shfl_xor_sync(0xFFFFFFFFu, cm, m2);
                    float os = __shfl_xor_sync(0xFFFFFFFFu, cs, m2);
                    float nm = fmaxf(cm, om);
                    cs = cs * __expf(cm - nm) + os * __expf(om - nm);
                    cm = nm;
                }
                acc[0][nt][h] = cm;
                acc[1][nt][h] = cs;
            }
        if (g == 0) {
#pragma unroll
            for (int nt = 0; nt < 8; ++nt)
#pragma unroll
                for (int h = 0; h < 2; ++h) {
                    int cloc = warp_n * 64 + nt * 8 + (c4 << 1) + h;
                    s_cms[cloc][warp_m] = acc[0][nt][h];
                    s_css[cloc][warp_m] = acc[1][nt][h];
                }
        }
    }
    __syncthreads();

    if (tid < 128) {
        float m0 = s_ms[tid][0], m1 = s_ms[tid][1];
        float m = fmaxf(m0, m1);
        float s = s_ss[tid][0] * __expf(m0 - m) + s_ss[tid][1] * __expf(m1 - m);
        g_mp[((size_t)b * 32 + ct) * HW + row0 + tid] = m;
        g_sp[((size_t)b * 32 + ct) * HW + row0 + tid] = s;
    }
    if (mirror && tid < 128) {
        float m = fmaxf(fmaxf(s_cms[tid][0], s_cms[tid][1]),
                        fmaxf(s_cms[tid][2], s_cms[tid][3]));
        float s = s_css[tid][0] * __expf(s_cms[tid][0] - m)
                + s_css[tid][1] * __expf(s_cms[tid][1] - m)
                + s_css[tid][2] * __expf(s_cms[tid][2] - m)
                + s_css[tid][3] * __expf(s_cms[tid][3] - m);
        g_mp[((size_t)b * 32 + rt) * HW + col0 + tid] = m;
        g_sp[((size_t)b * 32 + rt) * HW + col0 + tid] = s;
    }

    // 4) mirrored L store (transposed tile), coalesced
    if (mirror) {
        for (int i = tid; i < 8192; i += 256) {
            int trow = i >> 6;
            int tc2 = (i & 63) << 1;
            float2 v;
            v.x = s_t[tc2 * 129 + trow];
            v.y = s_t[(tc2 + 1) * 129 + trow];
            *(float2*)&Lout[(size_t)(col0 + trow) * HW + row0 + tc2] = v;
        }
    }
}

// ---------------- K3: combine per-tile partials -> m, 1/Z, e ----------------
__global__ __launch_bounds__(256) void rowcomb_kernel() {
    int r = blockIdx.x * 256 + threadIdx.x;
    int b = r >> 12, rr = r & (HW - 1);
    float m = -1e30f;
#pragma unroll
    for (int ctile = 0; ctile < 32; ++ctile)
        m = fmaxf(m, g_mp[((size_t)b * 32 + ctile) * HW + rr]);
    float s = 0.f;
#pragma unroll
    for (int ctile = 0; ctile < 32; ++ctile)
        s += g_sp[((size_t)b * 32 + ctile) * HW + rr]
             * __expf(g_mp[((size_t)b * 32 + ctile) * HW + rr] - m);
    float z = 1.0f / s;
    g_m[r] = m;
    g_zs[r] = z;
    g_E[r] = __expf(-m) * z;
}

// ---------------- top-3 helper ----------------
__device__ __forceinline__ void top3_insert(float v, float& a, float& b, float& c) {
    if (v > c) {
        if (v > a)      { c = b; b = a; a = v; }
        else if (v > b) { c = b; b = v; }
        else            { c = v; }
    }
}

// ---------------- K4: stats pass (S + top3), read-only over L ----------------
__global__ __launch_bounds__(256) void stats_kernel(float* __restrict__ out_val) {
    __shared__ float sE[HW];
    __shared__ float sS[256], sa[256], sb2[256], sc2[256];
    int r = blockIdx.x, b = r >> 12, sidx = r & (HW - 1);
    int tid = threadIdx.x;
    for (int i = tid << 2; i < HW; i += 1024)
        *(float4*)&sE[i] = *(const float4*)&g_E[(b << 12) + i];
    float ms = g_m[r], zs = g_zs[r];
    const float* Lr = g_L + (size_t)r * HW;
    __syncthreads();

    float S = 0.f, t0 = -1.f, t1 = -1.f, t2 = -1.f;
    for (int t = tid << 2; t < HW; t += 1024) {
        float4 L4 = *(const float4*)&Lr[t];
        float4 e4 = *(const float4*)&sE[t];
        float vx = __expf(2.f * L4.x - ms) * zs * e4.x;
        float vy = __expf(2.f * L4.y - ms) * zs * e4.y;
        float vz = __expf(2.f * L4.z - ms) * zs * e4.z;
        float vw = __expf(2.f * L4.w - ms) * zs * e4.w;
        S += (vx + vy) + (vz + vw);
        top3_insert(vx, t0, t1, t2);
        top3_insert(vy, t0, t1, t2);
        top3_insert(vz, t0, t1, t2);
        top3_insert(vw, t0, t1, t2);
    }
    sS[tid] = S; sa[tid] = t0; sb2[tid] = t1; sc2[tid] = t2;
    __syncthreads();
    for (int st = 128; st > 0; st >>= 1) {
        if (tid < st) {
            sS[tid] += sS[tid + st];
            float a0 = sa[tid + st], a1 = sb2[tid + st], a2 = sc2[tid + st];
            float b0 = sa[tid], b1 = sb2[tid], b2 = sc2[tid];
            top3_insert(a0, b0, b1, b2);
            top3_insert(a1, b0, b1, b2);
            top3_insert(a2, b0, b1, b2);
            sa[tid] = b0; sb2[tid] = b1; sc2[tid] = b2;
        }
        __syncthreads();
    }
    if (tid == 0) {
        g_S[r] = sS[0];
        out_val[(b * 3 + 0) * HW + sidx] = sa[0];
        out_val[(b * 3 + 1) * HW + sidx] = sb2[0];
        out_val[(b * 3 + 2) * HW + sidx] = sc2[0];
    }
}

// ---------------- K4b: w = e / (S + 1e-8) ----------------
__global__ __launch_bounds__(256) void srecip_kernel() {
    int i = blockIdx.x * 256 + threadIdx.x;
    g_W[i] = g_E[i] / (g_S[i] + 1e-8f);
}

// ---------------- K5: write scaled x_soft directly ----------------
__global__ __launch_bounds__(256) void write_kernel(float* __restrict__ out_soft) {
    __shared__ float sW[HW];
    int r = blockIdx.x, b = r >> 12;
    int tid = threadIdx.x;
    for (int i = tid << 2; i < HW; i += 1024)
        *(float4*)&sW[i] = *(const float4*)&g_W[(b << 12) + i];
    float ms = g_m[r], zs = g_zs[r];
    const float* Lr = g_L + (size_t)r * HW;
    float* Or = out_soft + (size_t)r * HW;
    __syncthreads();
    for (int t = tid << 2; t < HW; t += 1024) {
        float4 L4 = *(const float4*)&Lr[t];
        float4 w4 = *(const float4*)&sW[t];
        float4 v;
        v.x = __expf(2.f * L4.x - ms) * zs * w4.x;
        v.y = __expf(2.f * L4.y - ms) * zs * w4.y;
        v.z = __expf(2.f * L4.z - ms) * zs * w4.z;
        v.w = __expf(2.f * L4.w - ms) * zs * w4.w;
        *(float4*)&Or[t] = v;
    }
}

// ---------------- launch ----------------
extern "C" void kernel_launch(void* const* d_in, const int* in_sizes, int n_in,
                              void* d_out, int out_size) {
    const float* x = (const float*)d_in[0];
    const float* alpha = (const float*)d_in[1];
    float* out = (float*)d_out;
    float* out_val = out;                    // (2,3,64,64)
    float* out_soft = out + NB * 3 * HW;     // (2,4096,64,64)

    cudaFuncSetAttribute(gemm_mma_kernel,
                         cudaFuncAttributeMaxDynamicSharedMemorySize, 2 * STAGE);

    norm_part_kernel<<<dim3(32, 8), 256>>>(x);
    norm_fin_kernel<<<32, 256>>>();
    prep_kernel<<<dim3(128, 8, NB), 256>>>(x);
    gemm_mma_kernel<<<dim3(528, NB), 256, 2 * STAGE>>>(alpha);
    rowcomb_kernel<<<32, 256>>>();
    stats_kernel<<<NB * HW, 256>>>(out_val);
    srecip_kernel<<<32, 256>>>();
    write_kernel<<<NB * HW, 256>>>(out_soft);
}

// round 11
// speedup vs baseline: 3.7290x; 1.1229x over previous
#include <cuda_runtime.h>
#include <cuda_bf16.h>
#include <math.h>
#include <stdint.h>

#define NB 2
#define NC 256
#define HW 4096
#define HW2 (HW * HW)

// L in [-5,5] quantized to u16 with step 10/65536
#define ENCK 6553.6f
#define DECK2 3.0517578125e-4f   /* 20/65536 exact */

// ---------------- scratch (static __device__ globals; no allocations) ----------------
__device__ float g_part[8 * NB * HW];
__device__ float g_inv[NB * HW];
__device__ uint16_t g_Q[(size_t)NB * HW2];      // quantized logits (67 MB)
__device__ float g_sp[NB * 32 * HW];            // per (row, col-tile) partial sum of exp(L-5)
__device__ float g_zs[NB * HW];                 // 1 / Z   (Z = sum exp(L-5))
__device__ float g_S[NB * HW];                  // row sum of x_c
__device__ float g_W[NB * HW];                  // z_t / (S_t + 1e-8)
__device__ __nv_bfloat16 g_xh[(size_t)NB * HW * NC];   // normalized, [pixel][chan], hi
__device__ __nv_bfloat16 g_xl[(size_t)NB * HW * NC];   // residual lo

// ---------------- ptx helpers ----------------
static __device__ __forceinline__ uint32_t s2u(const void* p) {
    uint32_t a;
    asm("{ .reg .u64 t; cvta.to.shared.u64 t, %1; cvt.u32.u64 %0, t; }" : "=r"(a) : "l"(p));
    return a;
}
static __device__ __forceinline__ void cpa16(uint32_t dst, const void* src) {
    asm volatile("cp.async.cg.shared.global [%0], [%1], 16;" :: "r"(dst), "l"(src));
}
static __device__ __forceinline__ void ldm4(uint32_t* r, uint32_t a) {
    asm volatile("ldmatrix.sync.aligned.m8n8.x4.shared.b16 {%0,%1,%2,%3}, [%4];"
        : "=r"(r[0]), "=r"(r[1]), "=r"(r[2]), "=r"(r[3]) : "r"(a));
}
static __device__ __forceinline__ void mma16816(float* c, const uint32_t* a,
                                                uint32_t b0, uint32_t b1) {
    asm volatile("mma.sync.aligned.m16n8k16.row.col.f32.bf16.bf16.f32 "
        "{%0,%1,%2,%3}, {%4,%5,%6,%7}, {%8,%9}, {%0,%1,%2,%3};"
        : "+f"(c[0]), "+f"(c[1]), "+f"(c[2]), "+f"(c[3])
        : "r"(a[0]), "r"(a[1]), "r"(a[2]), "r"(a[3]), "r"(b0), "r"(b1));
}
static __device__ __forceinline__ uint32_t quant2(float L0, float L1) {
    int q0 = __float2int_rn((L0 + 5.0f) * ENCK);
    int q1 = __float2int_rn((L1 + 5.0f) * ENCK);
    q0 = min(max(q0, 0), 65535);
    q1 = min(max(q1, 0), 65535);
    return (uint32_t)q0 | ((uint32_t)q1 << 16);
}

// ---------------- K1a: partial sum of squares ----------------
__global__ __launch_bounds__(256) void norm_part_kernel(const float* __restrict__ x) {
    int p  = blockIdx.x * 256 + threadIdx.x;
    int cb = blockIdx.y;
    int b  = p >> 12;
    int pi = p & (HW - 1);
    const float* xb = x + (size_t)b * NC * HW + (size_t)cb * 32 * HW + pi;
    float s = 0.f;
#pragma unroll
    for (int c = 0; c < 32; ++c) { float v = xb[(size_t)c * HW]; s += v * v; }
    g_part[cb * (NB * HW) + p] = s;
}

// ---------------- K1b: finalize inverse norms ----------------
__global__ __launch_bounds__(256) void norm_fin_kernel() {
    int p = blockIdx.x * 256 + threadIdx.x;
    float s = 0.f;
#pragma unroll
    for (int cb = 0; cb < 8; ++cb) s += g_part[cb * (NB * HW) + p];
    g_inv[p] = 1.0f / fmaxf(sqrtf(s), 1e-12f);
}

// ---------------- K1c: normalize + split bf16 + transpose -> [p][c] ----------------
__global__ __launch_bounds__(256) void prep_kernel(const float* __restrict__ x) {
    __shared__ float sh[32][33];
    int p0 = blockIdx.x * 32, c0 = blockIdx.y * 32, b = blockIdx.z;
    int tx = threadIdx.x & 31, ty = threadIdx.x >> 5;
    const float* xb = x + (size_t)b * NC * HW;
#pragma unroll
    for (int i = 0; i < 4; ++i) {
        int c = c0 + ty + i * 8, p = p0 + tx;
        sh[ty + i * 8][tx] = xb[(size_t)c * HW + p] * g_inv[b * HW + p];
    }
    __syncthreads();
#pragma unroll
    for (int i = 0; i < 4; ++i) {
        int p = p0 + ty + i * 8, c = c0 + tx;
        float v = sh[tx][ty + i * 8];
        __nv_bfloat16 h = __float2bfloat16(v);
        float lo = v - __bfloat162float(h);
        size_t o = (size_t)(b * HW + p) * NC + c;
        g_xh[o] = h;
        g_xl[o] = __float2bfloat16(lo);
    }
}

// ---------------- K2: symmetric mma.sync bf16 GEMM + fused epilogue ----------
#define AST 80
#define BUF (128 * AST)
#define STAGE (4 * BUF)
#define NCH 8

__global__ __launch_bounds__(256, 2) void gemm_mma_kernel(const float* __restrict__ alpha_p) {
    extern __shared__ char dsm[];
    __shared__ float s_gt[64];
    __shared__ float s_ss[128][2];
    __shared__ float s_css[128][4];

    int tid = threadIdx.x, lane = tid & 31, wid = tid >> 5;
    int b = blockIdx.y;

    // decode upper-triangular tile (rt <= ct)
    int u = 527 - (int)blockIdx.x;
    int i_ = (int)((sqrtf(8.0f * u + 1.0f) - 1.0f) * 0.5f);
    while (i_ * (i_ + 1) / 2 > u) --i_;
    while ((i_ + 1) * (i_ + 2) / 2 <= u) ++i_;
    int j_ = u - i_ * (i_ + 1) / 2;
    int rt = 31 - i_, ct = 31 - j_;
    int row0 = rt * 128, col0 = ct * 128;
    bool mirror = (ct > rt);

    int warp_m = wid & 3, warp_n = wid >> 2;

    if (tid < 64) {
        float d = (float)tid;
        s_gt[tid] = expf(-d * d * (1.0f / (2.0f * 3.2f * 3.2f)));
    }

    const char* xh = (const char*)(g_xh + (size_t)b * HW * NC);
    const char* xl = (const char*)(g_xl + (size_t)b * HW * NC);
    uint32_t smb = s2u(dsm);

    float acc[2][8][4];
#pragma unroll
    for (int mt = 0; mt < 2; ++mt)
#pragma unroll
        for (int nt = 0; nt < 8; ++nt)
#pragma unroll
            for (int q = 0; q < 4; ++q) acc[mt][nt][q] = 0.f;

    // ---- prologue: load chunk 0 into stage 0 ----
#pragma unroll
    for (int i = 0; i < 8; ++i) {
        int buf = i >> 1;
        int rem = ((i & 1) << 8) + tid;
        int r = rem >> 2, cc = rem & 3;
        uint32_t so = (uint32_t)(buf * BUF + r * AST + cc * 16);
        size_t go = (size_t)(((buf & 2) ? col0 : row0) + r) * 512 + cc * 16;
        cpa16(smb + so, ((buf & 1) ? xl : xh) + go);
    }
    asm volatile("cp.async.commit_group;" ::: "memory");

    int grp = lane >> 3, rr8 = lane & 7;
    int aro = ((grp & 1) << 3) + rr8;
    int ako = (grp & 2) << 3;
    int bro = ((grp >> 1) << 3) + rr8;
    int bko = (grp & 1) << 4;

    for (int ch = 0; ch < NCH; ++ch) {
        asm volatile("cp.async.wait_group 0;" ::: "memory");
        __syncthreads();
        if (ch < NCH - 1) {
            uint32_t sb = smb + ((ch + 1) & 1) * STAGE;
            int kof = (ch + 1) * 64;
#pragma unroll
            for (int i = 0; i < 8; ++i) {
                int buf = i >> 1;
                int rem = ((i & 1) << 8) + tid;
                int r = rem >> 2, cc = rem & 3;
                uint32_t so = (uint32_t)(buf * BUF + r * AST + cc * 16);
                size_t go = (size_t)(((buf & 2) ? col0 : row0) + r) * 512 + kof + cc * 16;
                cpa16(sb + so, ((buf & 1) ? xl : xh) + go);
            }
            asm volatile("cp.async.commit_group;" ::: "memory");
        }
        uint32_t sb = smb + (ch & 1) * STAGE;
#pragma unroll
        for (int ks = 0; ks < 2; ++ks) {
            uint32_t ah[2][4], al[2][4];
#pragma unroll
            for (int mt = 0; mt < 2; ++mt) {
                int ar = warp_m * 32 + mt * 16 + aro;
                uint32_t ao = (uint32_t)(ar * AST + ks * 32 + ako);
                ldm4(ah[mt], sb + 0 * BUF + ao);
                ldm4(al[mt], sb + 1 * BUF + ao);
            }
#pragma unroll
            for (int p = 0; p < 4; ++p) {
                int br = warp_n * 64 + p * 16 + bro;
                uint32_t bo = (uint32_t)(br * AST + ks * 32 + bko);
                uint32_t bh_[4], bl_[4];
                ldm4(bh_, sb + 2 * BUF + bo);
                ldm4(bl_, sb + 3 * BUF + bo);
                mma16816(acc[0][2 * p],     ah[0], bh_[0], bh_[1]);
                mma16816(acc[0][2 * p + 1], ah[0], bh_[2], bh_[3]);
                mma16816(acc[1][2 * p],     ah[1], bh_[0], bh_[1]);
                mma16816(acc[1][2 * p + 1], ah[1], bh_[2], bh_[3]);
                mma16816(acc[0][2 * p],     al[0], bh_[0], bh_[1]);
                mma16816(acc[0][2 * p + 1], al[0], bh_[2], bh_[3]);
                mma16816(acc[1][2 * p],     al[1], bh_[0], bh_[1]);
                mma16816(acc[1][2 * p + 1], al[1], bh_[2], bh_[3]);
                mma16816(acc[0][2 * p],     ah[0], bl_[0], bl_[1]);
                mma16816(acc[0][2 * p + 1], ah[0], bl_[2], bl_[3]);
                mma16816(acc[1][2 * p],     ah[1], bl_[0], bl_[1]);
                mma16816(acc[1][2 * p + 1], ah[1], bl_[2], bl_[3]);
            }
        }
    }
    __syncthreads();   // stage buffers dead; s_t may alias dsm

    // ---- epilogue (fixed-shift softmax: P = exp(L-5), no maxes) ----
    float alpha = *alpha_p;
    int g = lane >> 2, c4 = lane & 3;
    uint16_t* Qout = g_Q + (size_t)b * HW2;
    float* s_t = (float*)dsm;          // [128][129] L staging for mirror (66 KB)

    // 1) L -> quantized store; pv = exp(L-5) kept in acc
#pragma unroll
    for (int mt = 0; mt < 2; ++mt)
#pragma unroll
        for (int half = 0; half < 2; ++half) {
            int rloc = warp_m * 32 + mt * 16 + half * 8 + g;
            int srow = row0 + rloc;
            int sr = srow >> 6, sc = srow & 63;
#pragma unroll
            for (int nt = 0; nt < 8; ++nt) {
                int cbase = warp_n * 64 + nt * 8 + (c4 << 1);
                float Lv[2];
#pragma unroll
                for (int h = 0; h < 2; ++h) {
                    int tcol = col0 + cbase + h;
                    int tr = tcol >> 6, tc = tcol & 63;
                    int dr = sr - tr; dr = dr < 0 ? -dr : dr;
                    int dc = sc - tc; dc = dc < 0 ? -dc : dc;
                    float L = acc[mt][nt][half * 2 + h] * alpha
                              * (1.0f - s_gt[dr] * s_gt[dc]);
                    Lv[h] = L;
                    acc[mt][nt][half * 2 + h] = __expf(L - 5.0f);
                }
                *(uint32_t*)&Qout[(size_t)srow * HW + col0 + cbase] = quant2(Lv[0], Lv[1]);
                if (mirror) {
                    s_t[rloc * 129 + cbase]     = Lv[0];
                    s_t[rloc * 129 + cbase + 1] = Lv[1];
                }
            }
        }

    // 2) row partial sums of P
#pragma unroll
    for (int mt = 0; mt < 2; ++mt)
#pragma unroll
        for (int half = 0; half < 2; ++half) {
            int rloc = warp_m * 32 + mt * 16 + half * 8 + g;
            float rs = 0.f;
#pragma unroll
            for (int nt = 0; nt < 8; ++nt)
                rs += acc[mt][nt][half * 2] + acc[mt][nt][half * 2 + 1];
            rs += __shfl_xor_sync(0xFFFFFFFFu, rs, 1);
            rs += __shfl_xor_sync(0xFFFFFFFFu, rs, 2);
            if (c4 == 0) s_ss[rloc][warp_n] = rs;
        }

    // 3) column partial sums (mirror only)
    if (mirror) {
#pragma unroll
        for (int nt = 0; nt < 8; ++nt)
#pragma unroll
            for (int h = 0; h < 2; ++h) {
                float cs = acc[0][nt][h] + acc[0][nt][2 + h]
                         + acc[1][nt][h] + acc[1][nt][2 + h];
                cs += __shfl_xor_sync(0xFFFFFFFFu, cs, 4);
                cs += __shfl_xor_sync(0xFFFFFFFFu, cs, 8);
                cs += __shfl_xor_sync(0xFFFFFFFFu, cs, 16);
                if (g == 0) {
                    int cloc = warp_n * 64 + nt * 8 + (c4 << 1) + h;
                    s_css[cloc][warp_m] = cs;
                }
            }
    }
    __syncthreads();

    if (tid < 128) {
        g_sp[((size_t)b * 32 + ct) * HW + row0 + tid] = s_ss[tid][0] + s_ss[tid][1];
    }
    if (mirror && tid < 128) {
        g_sp[((size_t)b * 32 + rt) * HW + col0 + tid] =
            s_css[tid][0] + s_css[tid][1] + s_css[tid][2] + s_css[tid][3];
    }

    // 4) mirrored quantized store (transposed), coalesced
    if (mirror) {
        for (int i = tid; i < 8192; i += 256) {
            int trow = i >> 6;
            int tc2 = (i & 63) << 1;
            float L0 = s_t[tc2 * 129 + trow];
            float L1 = s_t[(tc2 + 1) * 129 + trow];
            *(uint32_t*)&Qout[(size_t)(col0 + trow) * HW + row0 + tc2] = quant2(L0, L1);
        }
    }
}

// ---------------- K3: combine per-tile partials -> 1/Z ----------------
__global__ __launch_bounds__(256) void rowcomb_kernel() {
    int r = blockIdx.x * 256 + threadIdx.x;
    int b = r >> 12, rr = r & (HW - 1);
    float s = 0.f;
#pragma unroll
    for (int ctile = 0; ctile < 32; ++ctile)
        s += g_sp[((size_t)b * 32 + ctile) * HW + rr];
    g_zs[r] = 1.0f / s;
}

// ---------------- top-3 helper ----------------
__device__ __forceinline__ void top3_insert(float v, float& a, float& b, float& c) {
    if (v > c) {
        if (v > a)      { c = b; b = a; a = v; }
        else if (v > b) { c = b; b = v; }
        else            { c = v; }
    }
}

// ---------------- decode 8 u16 -> floats ----------------
__device__ __forceinline__ void dec8(uint4 pk, float* f) {
    f[0] = (float)(pk.x & 0xFFFF); f[1] = (float)(pk.x >> 16);
    f[2] = (float)(pk.y & 0xFFFF); f[3] = (float)(pk.y >> 16);
    f[4] = (float)(pk.z & 0xFFFF); f[5] = (float)(pk.z >> 16);
    f[6] = (float)(pk.w & 0xFFFF); f[7] = (float)(pk.w >> 16);
}

// ---------------- K4: stats pass (S + top3), read-only over Q ----------------
__global__ __launch_bounds__(256) void stats_kernel(float* __restrict__ out_val) {
    __shared__ float sZ[HW];
    __shared__ float sS[256], sa[256], sb2[256], sc2[256];
    int r = blockIdx.x, b = r >> 12, sidx = r & (HW - 1);
    int tid = threadIdx.x;
    for (int i = tid << 2; i < HW; i += 1024)
        *(float4*)&sZ[i] = *(const float4*)&g_zs[(b << 12) + i];
    float zs = g_zs[r];
    const uint16_t* Qr = g_Q + (size_t)r * HW;
    __syncthreads();

    float S = 0.f, t0 = -1.f, t1 = -1.f, t2 = -1.f;
#pragma unroll
    for (int part = 0; part < 2; ++part) {
        int t0i = (part * 256 + tid) * 8;
        uint4 pk = *(const uint4*)(Qr + t0i);
        float f[8];
        dec8(pk, f);
#pragma unroll
        for (int j = 0; j < 8; ++j) {
            float uu = __expf(fmaf(f[j], DECK2, -20.0f)) * sZ[t0i + j];
            S += uu;
            top3_insert(uu, t0, t1, t2);
        }
    }
    sS[tid] = S; sa[tid] = t0; sb2[tid] = t1; sc2[tid] = t2;
    __syncthreads();
    for (int st = 128; st > 0; st >>= 1) {
        if (tid < st) {
            sS[tid] += sS[tid + st];
            float a0 = sa[tid + st], a1 = sb2[tid + st], a2 = sc2[tid + st];
            float b0 = sa[tid], b1 = sb2[tid], b2 = sc2[tid];
            top3_insert(a0, b0, b1, b2);
            top3_insert(a1, b0, b1, b2);
            top3_insert(a2, b0, b1, b2);
            sa[tid] = b0; sb2[tid] = b1; sc2[tid] = b2;
        }
        __syncthreads();
    }
    if (tid == 0) {
        g_S[r] = zs * sS[0];
        out_val[(b * 3 + 0) * HW + sidx] = zs * sa[0];
        out_val[(b * 3 + 1) * HW + sidx] = zs * sb2[0];
        out_val[(b * 3 + 2) * HW + sidx] = zs * sc2[0];
    }
}

// ---------------- K4b: w = z / (S + 1e-8) ----------------
__global__ __launch_bounds__(256) void srecip_kernel() {
    int i = blockIdx.x * 256 + threadIdx.x;
    g_W[i] = g_zs[i] / (g_S[i] + 1e-8f);
}

// ---------------- K5: write scaled x_soft directly ----------------
__global__ __launch_bounds__(256) void write_kernel(float* __restrict__ out_soft) {
    __shared__ float sW[HW];
    int r = blockIdx.x, b = r >> 12;
    int tid = threadIdx.x;
    for (int i = tid << 2; i < HW; i += 1024)
        *(float4*)&sW[i] = *(const float4*)&g_W[(b << 12) + i];
    float zs = g_zs[r];
    const uint16_t* Qr = g_Q + (size_t)r * HW;
    float* Or = out_soft + (size_t)r * HW;
    __syncthreads();
#pragma unroll
    for (int part = 0; part < 2; ++part) {
        int t0i = (part * 256 + tid) * 8;
        uint4 pk = *(const uint4*)(Qr + t0i);
        float f[8];
        dec8(pk, f);
        float4 v0, v1;
        v0.x = __expf(fmaf(f[0], DECK2, -20.0f)) * (zs * sW[t0i + 0]);
        v0.y = __expf(fmaf(f[1], DECK2, -20.0f)) * (zs * sW[t0i + 1]);
        v0.z = __expf(fmaf(f[2], DECK2, -20.0f)) * (zs * sW[t0i + 2]);
        v0.w = __expf(fmaf(f[3], DECK2, -20.0f)) * (zs * sW[t0i + 3]);
        v1.x = __expf(fmaf(f[4], DECK2, -20.0f)) * (zs * sW[t0i + 4]);
        v1.y = __expf(fmaf(f[5], DECK2, -20.0f)) * (zs * sW[t0i + 5]);
        v1.z = __expf(fmaf(f[6], DECK2, -20.0f)) * (zs * sW[t0i + 6]);
        v1.w = __expf(fmaf(f[7], DECK2, -20.0f)) * (zs * sW[t0i + 7]);
        *(float4*)&Or[t0i]     = v0;
        *(float4*)&Or[t0i + 4] = v1;
    }
}

// ---------------- launch ----------------
extern "C" void kernel_launch(void* const* d_in, const int* in_sizes, int n_in,
                              void* d_out, int out_size) {
    const float* x = (const float*)d_in[0];
    const float* alpha = (const float*)d_in[1];
    float* out = (float*)d_out;
    float* out_val = out;                    // (2,3,64,64)
    float* out_soft = out + NB * 3 * HW;     // (2,4096,64,64)

    cudaFuncSetAttribute(gemm_mma_kernel,
                         cudaFuncAttributeMaxDynamicSharedMemorySize, 2 * STAGE);

    norm_part_kernel<<<dim3(32, 8), 256>>>(x);
    norm_fin_kernel<<<32, 256>>>();
    prep_kernel<<<dim3(128, 8, NB), 256>>>(x);
    gemm_mma_kernel<<<dim3(528, NB), 256, 2 * STAGE>>>(alpha);
    rowcomb_kernel<<<32, 256>>>();
    stats_kernel<<<NB * HW, 256>>>(out_val);
    srecip_kernel<<<32, 256>>>();
    write_kernel<<<NB * HW, 256>>>(out_soft);
}

// round 13
// speedup vs baseline: 4.0772x; 1.0934x over previous
#include <cuda_runtime.h>
#include <cuda_bf16.h>
#include <math.h>
#include <stdint.h>

#define NB 2
#define NC 256
#define HW 4096
#define HW2 (HW * HW)

// L in [-5,5] quantized to u16 with step 10/65536
#define ENCK 6553.6f
#define DECK2 3.0517578125e-4f   /* 20/65536 exact */

// ---------------- scratch (static __device__ globals; no allocations) ----------------
__device__ uint16_t g_Q[(size_t)NB * HW2];      // quantized logits (67 MB)
__device__ float g_sp[NB * 32 * HW];            // per (row, col-tile) partial sum of exp(L-5)
__device__ float g_zs[NB * HW];                 // 1 / Z   (Z = sum exp(L-5))
__device__ float g_S[NB * HW];                  // row sum of x_c
__device__ float g_W[NB * HW];                  // z_t / (S_t + 1e-8)
__device__ __nv_bfloat16 g_xh[(size_t)NB * HW * NC];   // normalized, [pixel][chan], hi
__device__ __nv_bfloat16 g_xl[(size_t)NB * HW * NC];   // residual lo

// ---------------- ptx helpers ----------------
static __device__ __forceinline__ uint32_t s2u(const void* p) {
    uint32_t a;
    asm("{ .reg .u64 t; cvta.to.shared.u64 t, %1; cvt.u32.u64 %0, t; }" : "=r"(a) : "l"(p));
    return a;
}
static __device__ __forceinline__ void cpa16(uint32_t dst, const void* src) {
    asm volatile("cp.async.cg.shared.global [%0], [%1], 16;" :: "r"(dst), "l"(src));
}
static __device__ __forceinline__ void ldm4(uint32_t* r, uint32_t a) {
    asm volatile("ldmatrix.sync.aligned.m8n8.x4.shared.b16 {%0,%1,%2,%3}, [%4];"
        : "=r"(r[0]), "=r"(r[1]), "=r"(r[2]), "=r"(r[3]) : "r"(a));
}
static __device__ __forceinline__ void mma16816(float* c, const uint32_t* a,
                                                uint32_t b0, uint32_t b1) {
    asm volatile("mma.sync.aligned.m16n8k16.row.col.f32.bf16.bf16.f32 "
        "{%0,%1,%2,%3}, {%4,%5,%6,%7}, {%8,%9}, {%0,%1,%2,%3};"
        : "+f"(c[0]), "+f"(c[1]), "+f"(c[2]), "+f"(c[3])
        : "r"(a[0]), "r"(a[1]), "r"(a[2]), "r"(a[3]), "r"(b0), "r"(b1));
}
static __device__ __forceinline__ uint32_t quant2(float L0, float L1) {
    int q0 = __float2int_rn((L0 + 5.0f) * ENCK);
    int q1 = __float2int_rn((L1 + 5.0f) * ENCK);
    q0 = min(max(q0, 0), 65535);
    q1 = min(max(q1, 0), 65535);
    return (uint32_t)q0 | ((uint32_t)q1 << 16);
}

// ---------------- K1: fused normalize + split bf16 + transpose -> [p][c] ----------
// one block = 32 pixels x all 256 channels (single read of x); grid (HW/32, NB)
__global__ __launch_bounds__(256) void normprep_kernel(const float* __restrict__ x) {
    __shared__ float sh[256 * 33];     // sh[c*33 + p]
    __shared__ float ssum[32][9];
    __shared__ float sinv[32];
    int p0 = blockIdx.x * 32, b = blockIdx.y;
    int tid = threadIdx.x;
    int tx = tid & 31, ty = tid >> 5;
    const float* xb = x + (size_t)b * NC * HW;
#pragma unroll
    for (int i = 0; i < 32; ++i) {
        int c = i * 8 + ty;
        sh[c * 33 + tx] = xb[(size_t)c * HW + p0 + tx];
    }
    __syncthreads();
    float s = 0.f;
#pragma unroll
    for (int j = 0; j < 32; ++j) {
        float v = sh[(ty * 32 + j) * 33 + tx];
        s += v * v;
    }
    ssum[tx][ty] = s;
    __syncthreads();
    if (tid < 32) {
        float t = 0.f;
#pragma unroll
        for (int k = 0; k < 8; ++k) t += ssum[tid][k];
        sinv[tid] = 1.0f / fmaxf(sqrtf(t), 1e-12f);
    }
    __syncthreads();
#pragma unroll
    for (int i = 0; i < 32; ++i) {
        int c = tid, pl = i;
        float v = sh[c * 33 + pl] * sinv[pl];
        __nv_bfloat16 h = __float2bfloat16(v);
        float lo = v - __bfloat162float(h);
        size_t o = (size_t)(b * HW + p0 + pl) * NC + c;
        g_xh[o] = h;
        g_xl[o] = __float2bfloat16(lo);
    }
}

// ---------------- K2: symmetric mma.sync bf16 GEMM + fused epilogue ----------
#define AST 80
#define BUF (128 * AST)
#define STAGE (4 * BUF)
#define NCH 8

__global__ __launch_bounds__(256, 2) void gemm_mma_kernel(const float* __restrict__ alpha_p) {
    extern __shared__ char dsm[];
    __shared__ float s_gt[64];
    __shared__ float s_ss[128][2];
    __shared__ float s_css[128][4];

    int tid = threadIdx.x, lane = tid & 31, wid = tid >> 5;
    int b = blockIdx.y;

    // decode upper-triangular tile (rt <= ct)
    int u = 527 - (int)blockIdx.x;
    int i_ = (int)((sqrtf(8.0f * u + 1.0f) - 1.0f) * 0.5f);
    while (i_ * (i_ + 1) / 2 > u) --i_;
    while ((i_ + 1) * (i_ + 2) / 2 <= u) ++i_;
    int j_ = u - i_ * (i_ + 1) / 2;
    int rt = 31 - i_, ct = 31 - j_;
    int row0 = rt * 128, col0 = ct * 128;
    bool mirror = (ct > rt);

    int warp_m = wid & 3, warp_n = wid >> 2;

    if (tid < 64) {
        float d = (float)tid;
        s_gt[tid] = expf(-d * d * (1.0f / (2.0f * 3.2f * 3.2f)));
    }

    const char* xh = (const char*)(g_xh + (size_t)b * HW * NC);
    const char* xl = (const char*)(g_xl + (size_t)b * HW * NC);
    uint32_t smb = s2u(dsm);

    float acc[2][8][4];
#pragma unroll
    for (int mt = 0; mt < 2; ++mt)
#pragma unroll
        for (int nt = 0; nt < 8; ++nt)
#pragma unroll
            for (int q = 0; q < 4; ++q) acc[mt][nt][q] = 0.f;

    // ---- prologue: load chunk 0 into stage 0 ----
#pragma unroll
    for (int i = 0; i < 8; ++i) {
        int buf = i >> 1;
        int rem = ((i & 1) << 8) + tid;
        int r = rem >> 2, cc = rem & 3;
        uint32_t so = (uint32_t)(buf * BUF + r * AST + cc * 16);
        size_t go = (size_t)(((buf & 2) ? col0 : row0) + r) * 512 + cc * 16;
        cpa16(smb + so, ((buf & 1) ? xl : xh) + go);
    }
    asm volatile("cp.async.commit_group;" ::: "memory");

    int grp = lane >> 3, rr8 = lane & 7;
    int aro = ((grp & 1) << 3) + rr8;
    int ako = (grp & 2) << 3;
    int bro = ((grp >> 1) << 3) + rr8;
    int bko = (grp & 1) << 4;

    for (int ch = 0; ch < NCH; ++ch) {
        asm volatile("cp.async.wait_group 0;" ::: "memory");
        __syncthreads();
        if (ch < NCH - 1) {
            uint32_t sb = smb + ((ch + 1) & 1) * STAGE;
            int kof = (ch + 1) * 64;
#pragma unroll
            for (int i = 0; i < 8; ++i) {
                int buf = i >> 1;
                int rem = ((i & 1) << 8) + tid;
                int r = rem >> 2, cc = rem & 3;
                uint32_t so = (uint32_t)(buf * BUF + r * AST + cc * 16);
                size_t go = (size_t)(((buf & 2) ? col0 : row0) + r) * 512 + kof + cc * 16;
                cpa16(sb + so, ((buf & 1) ? xl : xh) + go);
            }
            asm volatile("cp.async.commit_group;" ::: "memory");
        }
        uint32_t sb = smb + (ch & 1) * STAGE;
#pragma unroll
        for (int ks = 0; ks < 2; ++ks) {
            uint32_t ah[2][4], al[2][4];
#pragma unroll
            for (int mt = 0; mt < 2; ++mt) {
                int ar = warp_m * 32 + mt * 16 + aro;
                uint32_t ao = (uint32_t)(ar * AST + ks * 32 + ako);
                ldm4(ah[mt], sb + 0 * BUF + ao);
                ldm4(al[mt], sb + 1 * BUF + ao);
            }
#pragma unroll
            for (int p = 0; p < 4; ++p) {
                int br = warp_n * 64 + p * 16 + bro;
                uint32_t bo = (uint32_t)(br * AST + ks * 32 + bko);
                uint32_t bh_[4], bl_[4];
                ldm4(bh_, sb + 2 * BUF + bo);
                ldm4(bl_, sb + 3 * BUF + bo);
                mma16816(acc[0][2 * p],     ah[0], bh_[0], bh_[1]);
                mma16816(acc[0][2 * p + 1], ah[0], bh_[2], bh_[3]);
                mma16816(acc[1][2 * p],     ah[1], bh_[0], bh_[1]);
                mma16816(acc[1][2 * p + 1], ah[1], bh_[2], bh_[3]);
                mma16816(acc[0][2 * p],     al[0], bh_[0], bh_[1]);
                mma16816(acc[0][2 * p + 1], al[0], bh_[2], bh_[3]);
                mma16816(acc[1][2 * p],     al[1], bh_[0], bh_[1]);
                mma16816(acc[1][2 * p + 1], al[1], bh_[2], bh_[3]);
                mma16816(acc[0][2 * p],     ah[0], bl_[0], bl_[1]);
                mma16816(acc[0][2 * p + 1], ah[0], bl_[2], bl_[3]);
                mma16816(acc[1][2 * p],     ah[1], bl_[0], bl_[1]);
                mma16816(acc[1][2 * p + 1], ah[1], bl_[2], bl_[3]);
            }
        }
    }
    __syncthreads();   // stage buffers dead; s_tq may alias dsm

    // ---- epilogue (fixed-shift softmax: P = exp(L-5), no maxes) ----
    float alpha = *alpha_p;
    int g = lane >> 2, c4 = lane & 3;
    uint16_t* Qout = g_Q + (size_t)b * HW2;
    uint16_t* s_tq = (uint16_t*)dsm;   // [128][130] quantized staging (33.3 KB)

    // 1) L -> quantized store; pv = exp(L-5) kept in acc
#pragma unroll
    for (int mt = 0; mt < 2; ++mt)
#pragma unroll
        for (int half = 0; half < 2; ++half) {
            int rloc = warp_m * 32 + mt * 16 + half * 8 + g;
            int srow = row0 + rloc;
            int sr = srow >> 6, sc = srow & 63;
#pragma unroll
            for (int nt = 0; nt < 8; ++nt) {
                int cbase = warp_n * 64 + nt * 8 + (c4 << 1);
                float Lv[2];
#pragma unroll
                for (int h = 0; h < 2; ++h) {
                    int tcol = col0 + cbase + h;
                    int tr = tcol >> 6, tc = tcol & 63;
                    int dr = sr - tr; dr = dr < 0 ? -dr : dr;
                    int dc = sc - tc; dc = dc < 0 ? -dc : dc;
                    float L = acc[mt][nt][half * 2 + h] * alpha
                              * (1.0f - s_gt[dr] * s_gt[dc]);
                    Lv[h] = L;
                    acc[mt][nt][half * 2 + h] = __expf(L - 5.0f);
                }
                uint32_t qp = quant2(Lv[0], Lv[1]);
                *(uint32_t*)&Qout[(size_t)srow * HW + col0 + cbase] = qp;
                if (mirror)
                    *(uint32_t*)&s_tq[rloc * 130 + cbase] = qp;
            }
        }

    // 2) row partial sums of P
#pragma unroll
    for (int mt = 0; mt < 2; ++mt)
#pragma unroll
        for (int half = 0; half < 2; ++half) {
            int rloc = warp_m * 32 + mt * 16 + half * 8 + g;
            float rs = 0.f;
#pragma unroll
            for (int nt = 0; nt < 8; ++nt)
                rs += acc[mt][nt][half * 2] + acc[mt][nt][half * 2 + 1];
            rs += __shfl_xor_sync(0xFFFFFFFFu, rs, 1);
            rs += __shfl_xor_sync(0xFFFFFFFFu, rs, 2);
            if (c4 == 0) s_ss[rloc][warp_n] = rs;
        }

    // 3) column partial sums (mirror only)
    if (mirror) {
#pragma unroll
        for (int nt = 0; nt < 8; ++nt)
#pragma unroll
            for (int h = 0; h < 2; ++h) {
                float cs = acc[0][nt][h] + acc[0][nt][2 + h]
                         + acc[1][nt][h] + acc[1][nt][2 + h];
                cs += __shfl_xor_sync(0xFFFFFFFFu, cs, 4);
                cs += __shfl_xor_sync(0xFFFFFFFFu, cs, 8);
                cs += __shfl_xor_sync(0xFFFFFFFFu, cs, 16);
                if (g == 0) {
                    int cloc = warp_n * 64 + nt * 8 + (c4 << 1) + h;
                    s_css[cloc][warp_m] = cs;
                }
            }
    }
    __syncthreads();

    if (tid < 128) {
        g_sp[((size_t)b * 32 + ct) * HW + row0 + tid] = s_ss[tid][0] + s_ss[tid][1];
    }
    if (mirror && tid < 128) {
        g_sp[((size_t)b * 32 + rt) * HW + col0 + tid] =
            s_css[tid][0] + s_css[tid][1] + s_css[tid][2] + s_css[tid][3];
    }

    // 4) mirrored quantized store (transposed), coalesced
    if (mirror) {
        for (int i = tid; i < 8192; i += 256) {
            int trow = i >> 6;
            int tc2 = (i & 63) << 1;
            uint32_t q0 = s_tq[tc2 * 130 + trow];
            uint32_t q1 = s_tq[(tc2 + 1) * 130 + trow];
            *(uint32_t*)&Qout[(size_t)(col0 + trow) * HW + row0 + tc2] = q0 | (q1 << 16);
        }
    }
}

// ---------------- K3: combine per-tile partials -> 1/Z ----------------
__global__ __launch_bounds__(256) void rowcomb_kernel() {
    int r = blockIdx.x * 256 + threadIdx.x;
    int b = r >> 12, rr = r & (HW - 1);
    float s = 0.f;
#pragma unroll
    for (int ctile = 0; ctile < 32; ++ctile)
        s += g_sp[((size_t)b * 32 + ctile) * HW + rr];
    g_zs[r] = 1.0f / s;
}

// ---------------- branchless top-3 insert ----------------
__device__ __forceinline__ void top3_insert(float v, float& a, float& b, float& c) {
    float m1 = fminf(a, v);
    a = fmaxf(a, v);
    float m2 = fminf(b, m1);
    b = fmaxf(b, m1);
    c = fmaxf(c, m2);
}

// ---------------- decode 8 u16 -> floats ----------------
__device__ __forceinline__ void dec8(uint4 pk, float* f) {
    f[0] = (float)(pk.x & 0xFFFF); f[1] = (float)(pk.x >> 16);
    f[2] = (float)(pk.y & 0xFFFF); f[3] = (float)(pk.y >> 16);
    f[4] = (float)(pk.z & 0xFFFF); f[5] = (float)(pk.z >> 16);
    f[6] = (float)(pk.w & 0xFFFF); f[7] = (float)(pk.w >> 16);
}

// ---------------- K4: stats pass (S + top3), read-only over Q ----------------
__global__ __launch_bounds__(256) void stats_kernel(float* __restrict__ out_val) {
    __shared__ float sZ[HW];
    __shared__ float sS[256], sa[256], sb2[256], sc2[256];
    int r = blockIdx.x, b = r >> 12, sidx = r & (HW - 1);
    int tid = threadIdx.x;
    for (int i = tid << 2; i < HW; i += 1024)
        *(float4*)&sZ[i] = *(const float4*)&g_zs[(b << 12) + i];
    float zs = g_zs[r];
    const uint16_t* Qr = g_Q + (size_t)r * HW;
    __syncthreads();

    float S = 0.f, t0 = -1.f, t1 = -1.f, t2 = -1.f;
#pragma unroll
    for (int part = 0; part < 2; ++part) {
        int t0i = (part * 256 + tid) * 8;
        uint4 pk = *(const uint4*)(Qr + t0i);
        float f[8];
        dec8(pk, f);
#pragma unroll
        for (int j = 0; j < 8; ++j) {
            float uu = __expf(fmaf(f[j], DECK2, -20.0f)) * sZ[t0i + j];
            S += uu;
            top3_insert(uu, t0, t1, t2);
        }
    }
    sS[tid] = S; sa[tid] = t0; sb2[tid] = t1; sc2[tid] = t2;
    __syncthreads();
    for (int st = 128; st > 0; st >>= 1) {
        if (tid < st) {
            sS[tid] += sS[tid + st];
            float a0 = sa[tid + st], a1 = sb2[tid + st], a2 = sc2[tid + st];
            float b0 = sa[tid], b1 = sb2[tid], b2 = sc2[tid];
            top3_insert(a0, b0, b1, b2);
            top3_insert(a1, b0, b1, b2);
            top3_insert(a2, b0, b1, b2);
            sa[tid] = b0; sb2[tid] = b1; sc2[tid] = b2;
        }
        __syncthreads();
    }
    if (tid == 0) {
        g_S[r] = zs * sS[0];
        out_val[(b * 3 + 0) * HW + sidx] = zs * sa[0];
        out_val[(b * 3 + 1) * HW + sidx] = zs * sb2[0];
        out_val[(b * 3 + 2) * HW + sidx] = zs * sc2[0];
    }
}

// ---------------- K4b: w = z / (S + 1e-8) ----------------
__global__ __launch_bounds__(256) void srecip_kernel() {
    int i = blockIdx.x * 256 + threadIdx.x;
    g_W[i] = g_zs[i] / (g_S[i] + 1e-8f);
}

// ---------------- K5: write scaled x_soft directly (streaming stores) ----------------
__global__ __launch_bounds__(256) void write_kernel(float* __restrict__ out_soft) {
    __shared__ float sW[HW];
    int r = blockIdx.x, b = r >> 12;
    int tid = threadIdx.x;
    for (int i = tid << 2; i < HW; i += 1024)
        *(float4*)&sW[i] = *(const float4*)&g_W[(b << 12) + i];
    float zs = g_zs[r];
    const uint16_t* Qr = g_Q + (size_t)r * HW;
    float* Or = out_soft + (size_t)r * HW;
    __syncthreads();
#pragma unroll
    for (int part = 0; part < 2; ++part) {
        int t0i = (part * 256 + tid) * 8;
        uint4 pk = *(const uint4*)(Qr + t0i);
        float f[8];
        dec8(pk, f);
        float4 v0, v1;
        v0.x = __expf(fmaf(f[0], DECK2, -20.0f)) * (zs * sW[t0i + 0]);
        v0.y = __expf(fmaf(f[1], DECK2, -20.0f)) * (zs * sW[t0i + 1]);
        v0.z = __expf(fmaf(f[2], DECK2, -20.0f)) * (zs * sW[t0i + 2]);
        v0.w = __expf(fmaf(f[3], DECK2, -20.0f)) * (zs * sW[t0i + 3]);
        v1.x = __expf(fmaf(f[4], DECK2, -20.0f)) * (zs * sW[t0i + 4]);
        v1.y = __expf(fmaf(f[5], DECK2, -20.0f)) * (zs * sW[t0i + 5]);
        v1.z = __expf(fmaf(f[6], DECK2, -20.0f)) * (zs * sW[t0i + 6]);
        v1.w = __expf(fmaf(f[7], DECK2, -20.0f)) * (zs * sW[t0i + 7]);
        __stcs((float4*)&Or[t0i],     v0);
        __stcs((float4*)&Or[t0i + 4], v1);
    }
}

// ---------------- launch ----------------
extern "C" void kernel_launch(void* const* d_in, const int* in_sizes, int n_in,
                              void* d_out, int out_size) {
    const float* x = (const float*)d_in[0];
    const float* alpha = (const float*)d_in[1];
    float* out = (float*)d_out;
    float* out_val = out;                    // (2,3,64,64)
    float* out_soft = out + NB * 3 * HW;     // (2,4096,64,64)

    cudaFuncSetAttribute(gemm_mma_kernel,
                         cudaFuncAttributeMaxDynamicSharedMemorySize, 2 * STAGE);

    normprep_kernel<<<dim3(HW / 32, NB), 256>>>(x);
    gemm_mma_kernel<<<dim3(528, NB), 256, 2 * STAGE>>>(alpha);
    rowcomb_kernel<<<32, 256>>>();
    stats_kernel<<<NB * HW, 256>>>(out_val);
    srecip_kernel<<<32, 256>>>();
    write_kernel<<<NB * HW, 256>>>(out_soft);
}

// round 14
// speedup vs baseline: 4.2451x; 1.0412x over previous
#include <cuda_runtime.h>
#include <cuda_bf16.h>
#include <math.h>
#include <stdint.h>

#define NB 2
#define NC 256
#define HW 4096
#define HW2 (HW * HW)

// L in [-5,5] quantized to u16 with step 10/65536
#define ENCK 6553.6f
#define DECK2 3.0517578125e-4f   /* 20/65536 exact */

// ---------------- scratch (static __device__ globals; no allocations) ----------------
__device__ uint16_t g_Q[(size_t)NB * HW2];      // quantized logits (67 MB)
__device__ float g_sp[NB * 32 * HW];            // per (row, col-tile) partial sum of exp(L-5)
__device__ float g_zs[NB * HW];                 // 1 / Z   (Z = sum exp(L-5))
__device__ float g_S[NB * HW];                  // row sum of x_c
__device__ float g_W[NB * HW];                  // z_t / (S_t + 1e-8)
__device__ __nv_bfloat16 g_xh[(size_t)NB * HW * NC];   // normalized, [pixel][chan], hi
__device__ __nv_bfloat16 g_xl[(size_t)NB * HW * NC];   // residual lo

// ---------------- ptx helpers ----------------
static __device__ __forceinline__ uint32_t s2u(const void* p) {
    uint32_t a;
    asm("{ .reg .u64 t; cvta.to.shared.u64 t, %1; cvt.u32.u64 %0, t; }" : "=r"(a) : "l"(p));
    return a;
}
static __device__ __forceinline__ void cpa16(uint32_t dst, const void* src) {
    asm volatile("cp.async.cg.shared.global [%0], [%1], 16;" :: "r"(dst), "l"(src));
}
static __device__ __forceinline__ void ldm4(uint32_t* r, uint32_t a) {
    asm volatile("ldmatrix.sync.aligned.m8n8.x4.shared.b16 {%0,%1,%2,%3}, [%4];"
        : "=r"(r[0]), "=r"(r[1]), "=r"(r[2]), "=r"(r[3]) : "r"(a));
}
static __device__ __forceinline__ void mma16816(float* c, const uint32_t* a,
                                                uint32_t b0, uint32_t b1) {
    asm volatile("mma.sync.aligned.m16n8k16.row.col.f32.bf16.bf16.f32 "
        "{%0,%1,%2,%3}, {%4,%5,%6,%7}, {%8,%9}, {%0,%1,%2,%3};"
        : "+f"(c[0]), "+f"(c[1]), "+f"(c[2]), "+f"(c[3])
        : "r"(a[0]), "r"(a[1]), "r"(a[2]), "r"(a[3]), "r"(b0), "r"(b1));
}
static __device__ __forceinline__ uint32_t quant2(float L0, float L1) {
    int q0 = __float2int_rn((L0 + 5.0f) * ENCK);
    int q1 = __float2int_rn((L1 + 5.0f) * ENCK);
    q0 = min(max(q0, 0), 65535);
    q1 = min(max(q1, 0), 65535);
    return (uint32_t)q0 | ((uint32_t)q1 << 16);
}

// ---------------- K1: fused normalize + split bf16 + transpose -> [p][c] ----------
__global__ __launch_bounds__(256) void normprep_kernel(const float* __restrict__ x) {
    __shared__ float sh[256 * 33];     // sh[c*33 + p]
    __shared__ float ssum[32][9];
    __shared__ float sinv[32];
    int p0 = blockIdx.x * 32, b = blockIdx.y;
    int tid = threadIdx.x;
    int tx = tid & 31, ty = tid >> 5;
    const float* xb = x + (size_t)b * NC * HW;
#pragma unroll
    for (int i = 0; i < 32; ++i) {
        int c = i * 8 + ty;
        sh[c * 33 + tx] = xb[(size_t)c * HW + p0 + tx];
    }
    __syncthreads();
    float s = 0.f;
#pragma unroll
    for (int j = 0; j < 32; ++j) {
        float v = sh[(ty * 32 + j) * 33 + tx];
        s += v * v;
    }
    ssum[tx][ty] = s;
    __syncthreads();
    if (tid < 32) {
        float t = 0.f;
#pragma unroll
        for (int k = 0; k < 8; ++k) t += ssum[tid][k];
        sinv[tid] = 1.0f / fmaxf(sqrtf(t), 1e-12f);
    }
    __syncthreads();
#pragma unroll
    for (int i = 0; i < 32; ++i) {
        int c = tid, pl = i;
        float v = sh[c * 33 + pl] * sinv[pl];
        __nv_bfloat16 h = __float2bfloat16(v);
        float lo = v - __bfloat162float(h);
        size_t o = (size_t)(b * HW + p0 + pl) * NC + c;
        g_xh[o] = h;
        g_xl[o] = __float2bfloat16(lo);
    }
}

// ---------------- K2: symmetric mma.sync bf16 GEMM + fused epilogue ----------
#define AST 80
#define BUF (128 * AST)
#define STAGE (4 * BUF)
#define NCH 8

__global__ __launch_bounds__(256, 2) void gemm_mma_kernel(const float* __restrict__ alpha_p) {
    extern __shared__ char dsm[];
    __shared__ float s_gt[64];
    __shared__ float s_ss[128][2];
    __shared__ float s_css[128][4];

    int tid = threadIdx.x, lane = tid & 31, wid = tid >> 5;
    int b = blockIdx.y;

    // decode upper-triangular tile (rt <= ct)
    int u = 527 - (int)blockIdx.x;
    int i_ = (int)((sqrtf(8.0f * u + 1.0f) - 1.0f) * 0.5f);
    while (i_ * (i_ + 1) / 2 > u) --i_;
    while ((i_ + 1) * (i_ + 2) / 2 <= u) ++i_;
    int j_ = u - i_ * (i_ + 1) / 2;
    int rt = 31 - i_, ct = 31 - j_;
    int row0 = rt * 128, col0 = ct * 128;
    bool mirror = (ct > rt);

    int warp_m = wid & 3, warp_n = wid >> 2;

    if (tid < 64) {
        float d = (float)tid;
        s_gt[tid] = expf(-d * d * (1.0f / (2.0f * 3.2f * 3.2f)));
    }

    const char* xh = (const char*)(g_xh + (size_t)b * HW * NC);
    const char* xl = (const char*)(g_xl + (size_t)b * HW * NC);
    uint32_t smb = s2u(dsm);

    float acc[2][8][4];
#pragma unroll
    for (int mt = 0; mt < 2; ++mt)
#pragma unroll
        for (int nt = 0; nt < 8; ++nt)
#pragma unroll
            for (int q = 0; q < 4; ++q) acc[mt][nt][q] = 0.f;

    // ---- prologue: load chunk 0 into stage 0 ----
#pragma unroll
    for (int i = 0; i < 8; ++i) {
        int buf = i >> 1;
        int rem = ((i & 1) << 8) + tid;
        int r = rem >> 2, cc = rem & 3;
        uint32_t so = (uint32_t)(buf * BUF + r * AST + cc * 16);
        size_t go = (size_t)(((buf & 2) ? col0 : row0) + r) * 512 + cc * 16;
        cpa16(smb + so, ((buf & 1) ? xl : xh) + go);
    }
    asm volatile("cp.async.commit_group;" ::: "memory");

    int grp = lane >> 3, rr8 = lane & 7;
    int aro = ((grp & 1) << 3) + rr8;
    int ako = (grp & 2) << 3;
    int bro = ((grp >> 1) << 3) + rr8;
    int bko = (grp & 1) << 4;

    for (int ch = 0; ch < NCH; ++ch) {
        asm volatile("cp.async.wait_group 0;" ::: "memory");
        __syncthreads();
        if (ch < NCH - 1) {
            uint32_t sb = smb + ((ch + 1) & 1) * STAGE;
            int kof = (ch + 1) * 64;
#pragma unroll
            for (int i = 0; i < 8; ++i) {
                int buf = i >> 1;
                int rem = ((i & 1) << 8) + tid;
                int r = rem >> 2, cc = rem & 3;
                uint32_t so = (uint32_t)(buf * BUF + r * AST + cc * 16);
                size_t go = (size_t)(((buf & 2) ? col0 : row0) + r) * 512 + kof + cc * 16;
                cpa16(sb + so, ((buf & 1) ? xl : xh) + go);
            }
            asm volatile("cp.async.commit_group;" ::: "memory");
        }
        uint32_t sb = smb + (ch & 1) * STAGE;
#pragma unroll
        for (int ks = 0; ks < 2; ++ks) {
            uint32_t ah[2][4], al[2][4];
#pragma unroll
            for (int mt = 0; mt < 2; ++mt) {
                int ar = warp_m * 32 + mt * 16 + aro;
                uint32_t ao = (uint32_t)(ar * AST + ks * 32 + ako);
                ldm4(ah[mt], sb + 0 * BUF + ao);
                ldm4(al[mt], sb + 1 * BUF + ao);
            }
#pragma unroll
            for (int pp = 0; pp < 2; ++pp) {
                int p0i = pp * 2, p1i = pp * 2 + 1;
                int br0 = warp_n * 64 + p0i * 16 + bro;
                int br1 = warp_n * 64 + p1i * 16 + bro;
                uint32_t bo0 = (uint32_t)(br0 * AST + ks * 32 + bko);
                uint32_t bo1 = (uint32_t)(br1 * AST + ks * 32 + bko);
                uint32_t bh0[4], bl0[4], bh1[4], bl1[4];
                ldm4(bh0, sb + 2 * BUF + bo0);
                ldm4(bl0, sb + 3 * BUF + bo0);
                ldm4(bh1, sb + 2 * BUF + bo1);
                ldm4(bl1, sb + 3 * BUF + bo1);
                // product-major: same-acc reuse distance = 8
                // hi*hi
                mma16816(acc[0][2 * p0i],     ah[0], bh0[0], bh0[1]);
                mma16816(acc[0][2 * p0i + 1], ah[0], bh0[2], bh0[3]);
                mma16816(acc[1][2 * p0i],     ah[1], bh0[0], bh0[1]);
                mma16816(acc[1][2 * p0i + 1], ah[1], bh0[2], bh0[3]);
                mma16816(acc[0][2 * p1i],     ah[0], bh1[0], bh1[1]);
                mma16816(acc[0][2 * p1i + 1], ah[0], bh1[2], bh1[3]);
                mma16816(acc[1][2 * p1i],     ah[1], bh1[0], bh1[1]);
                mma16816(acc[1][2 * p1i + 1], ah[1], bh1[2], bh1[3]);
                // lo*hi
                mma16816(acc[0][2 * p0i],     al[0], bh0[0], bh0[1]);
                mma16816(acc[0][2 * p0i + 1], al[0], bh0[2], bh0[3]);
                mma16816(acc[1][2 * p0i],     al[1], bh0[0], bh0[1]);
                mma16816(acc[1][2 * p0i + 1], al[1], bh0[2], bh0[3]);
                mma16816(acc[0][2 * p1i],     al[0], bh1[0], bh1[1]);
                mma16816(acc[0][2 * p1i + 1], al[0], bh1[2], bh1[3]);
                mma16816(acc[1][2 * p1i],     al[1], bh1[0], bh1[1]);
                mma16816(acc[1][2 * p1i + 1], al[1], bh1[2], bh1[3]);
                // hi*lo
                mma16816(acc[0][2 * p0i],     ah[0], bl0[0], bl0[1]);
                mma16816(acc[0][2 * p0i + 1], ah[0], bl0[2], bl0[3]);
                mma16816(acc[1][2 * p0i],     ah[1], bl0[0], bl0[1]);
                mma16816(acc[1][2 * p0i + 1], ah[1], bl0[2], bl0[3]);
                mma16816(acc[0][2 * p1i],     ah[0], bl1[0], bl1[1]);
                mma16816(acc[0][2 * p1i + 1], ah[0], bl1[2], bl1[3]);
                mma16816(acc[1][2 * p1i],     ah[1], bl1[0], bl1[1]);
                mma16816(acc[1][2 * p1i + 1], ah[1], bl1[2], bl1[3]);
            }
        }
    }
    __syncthreads();   // stage buffers dead; s_tq may alias dsm

    // ---- epilogue (fixed-shift softmax: P = exp(L-5), no maxes) ----
    float alpha = *alpha_p;
    int g = lane >> 2, c4 = lane & 3;
    uint16_t* Qout = g_Q + (size_t)b * HW2;
    uint16_t* s_tq = (uint16_t*)dsm;   // [128][130] quantized staging (33.3 KB)

    // 1) L -> quantized store; pv = exp(L-5) kept in acc
#pragma unroll
    for (int mt = 0; mt < 2; ++mt)
#pragma unroll
        for (int half = 0; half < 2; ++half) {
            int rloc = warp_m * 32 + mt * 16 + half * 8 + g;
            int srow = row0 + rloc;
            int sr = srow >> 6, sc = srow & 63;
#pragma unroll
            for (int nt = 0; nt < 8; ++nt) {
                int cbase = warp_n * 64 + nt * 8 + (c4 << 1);
                float Lv[2];
#pragma unroll
                for (int h = 0; h < 2; ++h) {
                    int tcol = col0 + cbase + h;
                    int tr = tcol >> 6, tc = tcol & 63;
                    int dr = sr - tr; dr = dr < 0 ? -dr : dr;
                    int dc = sc - tc; dc = dc < 0 ? -dc : dc;
                    float L = acc[mt][nt][half * 2 + h] * alpha
                              * (1.0f - s_gt[dr] * s_gt[dc]);
                    Lv[h] = L;
                    acc[mt][nt][half * 2 + h] = __expf(L - 5.0f);
                }
                uint32_t qp = quant2(Lv[0], Lv[1]);
                *(uint32_t*)&Qout[(size_t)srow * HW + col0 + cbase] = qp;
                if (mirror)
                    *(uint32_t*)&s_tq[rloc * 130 + cbase] = qp;
            }
        }

    // 2) row partial sums of P
#pragma unroll
    for (int mt = 0; mt < 2; ++mt)
#pragma unroll
        for (int half = 0; half < 2; ++half) {
            int rloc = warp_m * 32 + mt * 16 + half * 8 + g;
            float rs = 0.f;
#pragma unroll
            for (int nt = 0; nt < 8; ++nt)
                rs += acc[mt][nt][half * 2] + acc[mt][nt][half * 2 + 1];
            rs += __shfl_xor_sync(0xFFFFFFFFu, rs, 1);
            rs += __shfl_xor_sync(0xFFFFFFFFu, rs, 2);
            if (c4 == 0) s_ss[rloc][warp_n] = rs;
        }

    // 3) column partial sums (mirror only)
    if (mirror) {
#pragma unroll
        for (int nt = 0; nt < 8; ++nt)
#pragma unroll
            for (int h = 0; h < 2; ++h) {
                float cs = acc[0][nt][h] + acc[0][nt][2 + h]
                         + acc[1][nt][h] + acc[1][nt][2 + h];
                cs += __shfl_xor_sync(0xFFFFFFFFu, cs, 4);
                cs += __shfl_xor_sync(0xFFFFFFFFu, cs, 8);
                cs += __shfl_xor_sync(0xFFFFFFFFu, cs, 16);
                if (g == 0) {
                    int cloc = warp_n * 64 + nt * 8 + (c4 << 1) + h;
                    s_css[cloc][warp_m] = cs;
                }
            }
    }
    __syncthreads();

    if (tid < 128) {
        g_sp[((size_t)b * 32 + ct) * HW + row0 + tid] = s_ss[tid][0] + s_ss[tid][1];
    }
    if (mirror && tid < 128) {
        g_sp[((size_t)b * 32 + rt) * HW + col0 + tid] =
            s_css[tid][0] + s_css[tid][1] + s_css[tid][2] + s_css[tid][3];
    }

    // 4) mirrored quantized store (transposed), coalesced
    if (mirror) {
        for (int i = tid; i < 8192; i += 256) {
            int trow = i >> 6;
            int tc2 = (i & 63) << 1;
            uint32_t q0 = s_tq[tc2 * 130 + trow];
            uint32_t q1 = s_tq[(tc2 + 1) * 130 + trow];
            *(uint32_t*)&Qout[(size_t)(col0 + trow) * HW + row0 + tc2] = q0 | (q1 << 16);
        }
    }
}

// ---------------- K3: combine per-tile partials -> 1/Z ----------------
__global__ __launch_bounds__(256) void rowcomb_kernel() {
    int r = blockIdx.x * 256 + threadIdx.x;
    int b = r >> 12, rr = r & (HW - 1);
    float s = 0.f;
#pragma unroll
    for (int ctile = 0; ctile < 32; ++ctile)
        s += g_sp[((size_t)b * 32 + ctile) * HW + rr];
    g_zs[r] = 1.0f / s;
}

// ---------------- branchless top-3 insert ----------------
__device__ __forceinline__ void top3_insert(float v, float& a, float& b, float& c) {
    float m1 = fminf(a, v);
    a = fmaxf(a, v);
    float m2 = fminf(b, m1);
    b = fmaxf(b, m1);
    c = fmaxf(c, m2);
}

// ---------------- decode 8 u16 -> floats ----------------
__device__ __forceinline__ void dec8(uint4 pk, float* f) {
    f[0] = (float)(pk.x & 0xFFFF); f[1] = (float)(pk.x >> 16);
    f[2] = (float)(pk.y & 0xFFFF); f[3] = (float)(pk.y >> 16);
    f[4] = (float)(pk.z & 0xFFFF); f[5] = (float)(pk.z >> 16);
    f[6] = (float)(pk.w & 0xFFFF); f[7] = (float)(pk.w >> 16);
}

// ---------------- K4: stats pass (S + top3), read-only over Q ----------------
__global__ __launch_bounds__(256) void stats_kernel(float* __restrict__ out_val) {
    __shared__ float sS[256], sa[256], sb2[256], sc2[256];
    int r = blockIdx.x, b = r >> 12, sidx = r & (HW - 1);
    int tid = threadIdx.x;
    const float* zB = g_zs + (b << 12);
    float zs = g_zs[r];
    const uint16_t* Qr = g_Q + (size_t)r * HW;

    float S = 0.f, t0 = -1.f, t1 = -1.f, t2 = -1.f;
#pragma unroll
    for (int part = 0; part < 2; ++part) {
        int t0i = (part * 256 + tid) * 8;
        uint4 pk = *(const uint4*)(Qr + t0i);
        float4 z0 = *(const float4*)&zB[t0i];
        float4 z1 = *(const float4*)&zB[t0i + 4];
        float f[8];
        dec8(pk, f);
        float u0 = __expf(fmaf(f[0], DECK2, -20.0f)) * z0.x;
        float u1 = __expf(fmaf(f[1], DECK2, -20.0f)) * z0.y;
        float u2 = __expf(fmaf(f[2], DECK2, -20.0f)) * z0.z;
        float u3 = __expf(fmaf(f[3], DECK2, -20.0f)) * z0.w;
        float u4 = __expf(fmaf(f[4], DECK2, -20.0f)) * z1.x;
        float u5 = __expf(fmaf(f[5], DECK2, -20.0f)) * z1.y;
        float u6 = __expf(fmaf(f[6], DECK2, -20.0f)) * z1.z;
        float u7 = __expf(fmaf(f[7], DECK2, -20.0f)) * z1.w;
        S += ((u0 + u1) + (u2 + u3)) + ((u4 + u5) + (u6 + u7));
        top3_insert(u0, t0, t1, t2);
        top3_insert(u1, t0, t1, t2);
        top3_insert(u2, t0, t1, t2);
        top3_insert(u3, t0, t1, t2);
        top3_insert(u4, t0, t1, t2);
        top3_insert(u5, t0, t1, t2);
        top3_insert(u6, t0, t1, t2);
        top3_insert(u7, t0, t1, t2);
    }
    sS[tid] = S; sa[tid] = t0; sb2[tid] = t1; sc2[tid] = t2;
    __syncthreads();
    for (int st = 128; st > 0; st >>= 1) {
        if (tid < st) {
            sS[tid] += sS[tid + st];
            float a0 = sa[tid + st], a1 = sb2[tid + st], a2 = sc2[tid + st];
            float b0 = sa[tid], b1 = sb2[tid], b2 = sc2[tid];
            top3_insert(a0, b0, b1, b2);
            top3_insert(a1, b0, b1, b2);
            top3_insert(a2, b0, b1, b2);
            sa[tid] = b0; sb2[tid] = b1; sc2[tid] = b2;
        }
        __syncthreads();
    }
    if (tid == 0) {
        g_S[r] = zs * sS[0];
        out_val[(b * 3 + 0) * HW + sidx] = zs * sa[0];
        out_val[(b * 3 + 1) * HW + sidx] = zs * sb2[0];
        out_val[(b * 3 + 2) * HW + sidx] = zs * sc2[0];
    }
}

// ---------------- K4b: w = z / (S + 1e-8) ----------------
__global__ __launch_bounds__(256) void srecip_kernel() {
    int i = blockIdx.x * 256 + threadIdx.x;
    g_W[i] = g_zs[i] / (g_S[i] + 1e-8f);
}

// ---------------- K5: write scaled x_soft directly (streaming stores) ----------------
__global__ __launch_bounds__(256) void write_kernel(float* __restrict__ out_soft) {
    int r = blockIdx.x, b = r >> 12;
    int tid = threadIdx.x;
    const float* wB = g_W + (b << 12);
    float zs = g_zs[r];
    const uint16_t* Qr = g_Q + (size_t)r * HW;
    float* Or = out_soft + (size_t)r * HW;
#pragma unroll
    for (int part = 0; part < 2; ++part) {
        int t0i = (part * 256 + tid) * 8;
        uint4 pk = *(const uint4*)(Qr + t0i);
        float4 w0 = *(const float4*)&wB[t0i];
        float4 w1 = *(const float4*)&wB[t0i + 4];
        float f[8];
        dec8(pk, f);
        float4 v0, v1;
        v0.x = __expf(fmaf(f[0], DECK2, -20.0f)) * (zs * w0.x);
        v0.y = __expf(fmaf(f[1], DECK2, -20.0f)) * (zs * w0.y);
        v0.z = __expf(fmaf(f[2], DECK2, -20.0f)) * (zs * w0.z);
        v0.w = __expf(fmaf(f[3], DECK2, -20.0f)) * (zs * w0.w);
        v1.x = __expf(fmaf(f[4], DECK2, -20.0f)) * (zs * w1.x);
        v1.y = __expf(fmaf(f[5], DECK2, -20.0f)) * (zs * w1.y);
        v1.z = __expf(fmaf(f[6], DECK2, -20.0f)) * (zs * w1.z);
        v1.w = __expf(fmaf(f[7], DECK2, -20.0f)) * (zs * w1.w);
        __stcs((float4*)&Or[t0i],     v0);
        __stcs((float4*)&Or[t0i + 4], v1);
    }
}

// ---------------- launch ----------------
extern "C" void kernel_launch(void* const* d_in, const int* in_sizes, int n_in,
                              void* d_out, int out_size) {
    const float* x = (const float*)d_in[0];
    const float* alpha = (const float*)d_in[1];
    float* out = (float*)d_out;
    float* out_val = out;                    // (2,3,64,64)
    float* out_soft = out + NB * 3 * HW;     // (2,4096,64,64)

    cudaFuncSetAttribute(gemm_mma_kernel,
                         cudaFuncAttributeMaxDynamicSharedMemorySize, 2 * STAGE);

    normprep_kernel<<<dim3(HW / 32, NB), 256>>>(x);
    gemm_mma_kernel<<<dim3(528, NB), 256, 2 * STAGE>>>(alpha);
    rowcomb_kernel<<<32, 256>>>();
    stats_kernel<<<NB * HW, 256>>>(out_val);
    srecip_kernel<<<32, 256>>>();
    write_kernel<<<NB * HW, 256>>>(out_soft);
}

// round 15
// speedup vs baseline: 5.8932x; 1.3882x over previous
#include <cuda_runtime.h>
#include <cuda_fp16.h>
#include <math.h>
#include <stdint.h>

#define NB 2
#define NC 256
#define HW 4096
#define HW2 (HW * HW)

// L in [-5,5] quantized to u16 with step 10/65536
#define ENCK 6553.6f
#define DECK2 3.0517578125e-4f            /* 20/65536 exact */
#define DECK2L 4.402823871e-4f            /* DECK2 * log2(e) */
#define BIAS2 (-28.85390082f)             /* -20 * log2(e) */

// ---------------- scratch (static __device__ globals; no allocations) ----------------
__device__ uint16_t g_Q[(size_t)NB * HW2];      // quantized logits (67 MB)
__device__ float g_sp[NB * 32 * HW];            // per (row, col-tile) partial sum of exp(L-5)
__device__ float g_zs[NB * HW];                 // 1 / Z   (Z = sum exp(L-5))
__device__ float g_S[NB * HW];                  // row sum of x_c
__device__ float g_W[NB * HW];                  // z_t / (S_t + 1e-8)
__device__ __half g_xh[(size_t)NB * HW * NC];   // normalized fp16, [pixel][chan]

// ---------------- ptx helpers ----------------
static __device__ __forceinline__ uint32_t s2u(const void* p) {
    uint32_t a;
    asm("{ .reg .u64 t; cvta.to.shared.u64 t, %1; cvt.u32.u64 %0, t; }" : "=r"(a) : "l"(p));
    return a;
}
static __device__ __forceinline__ void cpa16(uint32_t dst, const void* src) {
    asm volatile("cp.async.cg.shared.global [%0], [%1], 16;" :: "r"(dst), "l"(src));
}
static __device__ __forceinline__ void ldm4(uint32_t* r, uint32_t a) {
    asm volatile("ldmatrix.sync.aligned.m8n8.x4.shared.b16 {%0,%1,%2,%3}, [%4];"
        : "=r"(r[0]), "=r"(r[1]), "=r"(r[2]), "=r"(r[3]) : "r"(a));
}
static __device__ __forceinline__ void mma16816(float* c, const uint32_t* a,
                                                uint32_t b0, uint32_t b1) {
    asm volatile("mma.sync.aligned.m16n8k16.row.col.f32.f16.f16.f32 "
        "{%0,%1,%2,%3}, {%4,%5,%6,%7}, {%8,%9}, {%0,%1,%2,%3};"
        : "+f"(c[0]), "+f"(c[1]), "+f"(c[2]), "+f"(c[3])
        : "r"(a[0]), "r"(a[1]), "r"(a[2]), "r"(a[3]), "r"(b0), "r"(b1));
}
static __device__ __forceinline__ uint32_t quant2(float L0, float L1) {
    int q0 = __float2int_rn((L0 + 5.0f) * ENCK);
    int q1 = __float2int_rn((L1 + 5.0f) * ENCK);
    q0 = min(max(q0, 0), 65535);
    q1 = min(max(q1, 0), 65535);
    return (uint32_t)q0 | ((uint32_t)q1 << 16);
}

// ---------------- K1: fused normalize + fp16 + transpose -> [p][c] ----------
__global__ __launch_bounds__(256) void normprep_kernel(const float* __restrict__ x) {
    __shared__ float sh[256 * 33];     // sh[c*33 + p]
    __shared__ float ssum[32][9];
    __shared__ float sinv[32];
    int p0 = blockIdx.x * 32, b = blockIdx.y;
    int tid = threadIdx.x;
    int tx = tid & 31, ty = tid >> 5;
    const float* xb = x + (size_t)b * NC * HW;
#pragma unroll
    for (int i = 0; i < 32; ++i) {
        int c = i * 8 + ty;
        sh[c * 33 + tx] = xb[(size_t)c * HW + p0 + tx];
    }
    __syncthreads();
    float s = 0.f;
#pragma unroll
    for (int j = 0; j < 32; ++j) {
        float v = sh[(ty * 32 + j) * 33 + tx];
        s += v * v;
    }
    ssum[tx][ty] = s;
    __syncthreads();
    if (tid < 32) {
        float t = 0.f;
#pragma unroll
        for (int k = 0; k < 8; ++k) t += ssum[tid][k];
        sinv[tid] = 1.0f / fmaxf(sqrtf(t), 1e-12f);
    }
    __syncthreads();
#pragma unroll
    for (int i = 0; i < 32; ++i) {
        int c = tid, pl = i;
        float v = sh[c * 33 + pl] * sinv[pl];
        g_xh[(size_t)(b * HW + p0 + pl) * NC + c] = __float2half_rn(v);
    }
}

// ---------------- K2: symmetric fp16 mma.sync GEMM + fused epilogue ----------
// 128B K-chunks (4 of them), stride 144 -> 2 stages x 2 bufs x 128 x 144 = 73728 B dsm
#define AST 144
#define BUF (128 * AST)
#define STAGE (2 * BUF)
#define NCH 4

__global__ __launch_bounds__(256, 2) void gemm_mma_kernel(const float* __restrict__ alpha_p) {
    extern __shared__ char dsm[];
    __shared__ float s_gt[64];
    __shared__ float s_ss[128][2];
    __shared__ float s_css[128][4];

    int tid = threadIdx.x, lane = tid & 31, wid = tid >> 5;
    int b = blockIdx.y;

    // decode upper-triangular tile (rt <= ct)
    int u = 527 - (int)blockIdx.x;
    int i_ = (int)((sqrtf(8.0f * u + 1.0f) - 1.0f) * 0.5f);
    while (i_ * (i_ + 1) / 2 > u) --i_;
    while ((i_ + 1) * (i_ + 2) / 2 <= u) ++i_;
    int j_ = u - i_ * (i_ + 1) / 2;
    int rt = 31 - i_, ct = 31 - j_;
    int row0 = rt * 128, col0 = ct * 128;
    bool mirror = (ct > rt);

    int warp_m = wid & 3, warp_n = wid >> 2;

    if (tid < 64) {
        float d = (float)tid;
        s_gt[tid] = expf(-d * d * (1.0f / (2.0f * 3.2f * 3.2f)));
    }

    const char* xh = (const char*)(g_xh + (size_t)b * HW * NC);
    uint32_t smb = s2u(dsm);

    float acc[2][8][4];
#pragma unroll
    for (int mt = 0; mt < 2; ++mt)
#pragma unroll
        for (int nt = 0; nt < 8; ++nt)
#pragma unroll
            for (int q = 0; q < 4; ++q) acc[mt][nt][q] = 0.f;

    // ---- prologue: load chunk 0 into stage 0 ----
#pragma unroll
    for (int i = 0; i < 8; ++i) {
        int buf = i >> 2;                       // 0=A(row0), 1=B(col0)
        int rem = ((i & 3) << 8) + tid;
        int r = rem >> 3, cc = rem & 7;
        uint32_t so = (uint32_t)(buf * BUF + r * AST + cc * 16);
        size_t go = (size_t)((buf ? col0 : row0) + r) * 512 + cc * 16;
        cpa16(smb + so, xh + go);
    }
    asm volatile("cp.async.commit_group;" ::: "memory");

    int grp = lane >> 3, rr8 = lane & 7;
    int aro = ((grp & 1) << 3) + rr8;
    int ako = (grp & 2) << 3;
    int bro = ((grp >> 1) << 3) + rr8;
    int bko = (grp & 1) << 4;

    for (int ch = 0; ch < NCH; ++ch) {
        asm volatile("cp.async.wait_group 0;" ::: "memory");
        __syncthreads();
        if (ch < NCH - 1) {
            uint32_t sb = smb + ((ch + 1) & 1) * STAGE;
            int kof = (ch + 1) * 128;           // byte offset within 512B row
#pragma unroll
            for (int i = 0; i < 8; ++i) {
                int buf = i >> 2;
                int rem = ((i & 3) << 8) + tid;
                int r = rem >> 3, cc = rem & 7;
                uint32_t so = (uint32_t)(buf * BUF + r * AST + cc * 16);
                size_t go = (size_t)((buf ? col0 : row0) + r) * 512 + kof + cc * 16;
                cpa16(sb + so, xh + go);
            }
            asm volatile("cp.async.commit_group;" ::: "memory");
        }
        uint32_t sb = smb + (ch & 1) * STAGE;
#pragma unroll
        for (int ks = 0; ks < 4; ++ks) {
            uint32_t ah[2][4];
#pragma unroll
            for (int mt = 0; mt < 2; ++mt) {
                int ar = warp_m * 32 + mt * 16 + aro;
                ldm4(ah[mt], sb + (uint32_t)(ar * AST + ks * 32 + ako));
            }
#pragma unroll
            for (int p = 0; p < 4; ++p) {
                int br = warp_n * 64 + p * 16 + bro;
                uint32_t bh_[4];
                ldm4(bh_, sb + BUF + (uint32_t)(br * AST + ks * 32 + bko));
                mma16816(acc[0][2 * p],     ah[0], bh_[0], bh_[1]);
                mma16816(acc[0][2 * p + 1], ah[0], bh_[2], bh_[3]);
                mma16816(acc[1][2 * p],     ah[1], bh_[0], bh_[1]);
                mma16816(acc[1][2 * p + 1], ah[1], bh_[2], bh_[3]);
            }
        }
    }
    __syncthreads();   // stage buffers dead; s_tq may alias dsm

    // ---- epilogue (fixed-shift softmax: P = exp(L-5), no maxes) ----
    float alpha = *alpha_p;
    int g = lane >> 2, c4 = lane & 3;
    uint16_t* Qout = g_Q + (size_t)b * HW2;
    uint16_t* s_tq = (uint16_t*)dsm;   // [128][130] quantized staging (33.3 KB)

    // 1) L -> quantized store; pv = exp(L-5) kept in acc
#pragma unroll
    for (int mt = 0; mt < 2; ++mt)
#pragma unroll
        for (int half = 0; half < 2; ++half) {
            int rloc = warp_m * 32 + mt * 16 + half * 8 + g;
            int srow = row0 + rloc;
            int sr = srow >> 6, sc = srow & 63;
#pragma unroll
            for (int nt = 0; nt < 8; ++nt) {
                int cbase = warp_n * 64 + nt * 8 + (c4 << 1);
                float Lv[2];
#pragma unroll
                for (int h = 0; h < 2; ++h) {
                    int tcol = col0 + cbase + h;
                    int tr = tcol >> 6, tc = tcol & 63;
                    int dr = sr - tr; dr = dr < 0 ? -dr : dr;
                    int dc = sc - tc; dc = dc < 0 ? -dc : dc;
                    float L = acc[mt][nt][half * 2 + h] * alpha
                              * (1.0f - s_gt[dr] * s_gt[dc]);
                    Lv[h] = L;
                    acc[mt][nt][half * 2 + h] = __expf(L - 5.0f);
                }
                uint32_t qp = quant2(Lv[0], Lv[1]);
                *(uint32_t*)&Qout[(size_t)srow * HW + col0 + cbase] = qp;
                if (mirror)
                    *(uint32_t*)&s_tq[rloc * 130 + cbase] = qp;
            }
        }

    // 2) row partial sums of P
#pragma unroll
    for (int mt = 0; mt < 2; ++mt)
#pragma unroll
        for (int half = 0; half < 2; ++half) {
            int rloc = warp_m * 32 + mt * 16 + half * 8 + g;
            float rs = 0.f;
#pragma unroll
            for (int nt = 0; nt < 8; ++nt)
                rs += acc[mt][nt][half * 2] + acc[mt][nt][half * 2 + 1];
            rs += __shfl_xor_sync(0xFFFFFFFFu, rs, 1);
            rs += __shfl_xor_sync(0xFFFFFFFFu, rs, 2);
            if (c4 == 0) s_ss[rloc][warp_n] = rs;
        }

    // 3) column partial sums (mirror only)
    if (mirror) {
#pragma unroll
        for (int nt = 0; nt < 8; ++nt)
#pragma unroll
            for (int h = 0; h < 2; ++h) {
                float cs = acc[0][nt][h] + acc[0][nt][2 + h]
                         + acc[1][nt][h] + acc[1][nt][2 + h];
                cs += __shfl_xor_sync(0xFFFFFFFFu, cs, 4);
                cs += __shfl_xor_sync(0xFFFFFFFFu, cs, 8);
                cs += __shfl_xor_sync(0xFFFFFFFFu, cs, 16);
                if (g == 0) {
                    int cloc = warp_n * 64 + nt * 8 + (c4 << 1) + h;
                    s_css[cloc][warp_m] = cs;
                }
            }
    }
    __syncthreads();

    if (tid < 128) {
        g_sp[((size_t)b * 32 + ct) * HW + row0 + tid] = s_ss[tid][0] + s_ss[tid][1];
    }
    if (mirror && tid < 128) {
        g_sp[((size_t)b * 32 + rt) * HW + col0 + tid] =
            s_css[tid][0] + s_css[tid][1] + s_css[tid][2] + s_css[tid][3];
    }

    // 4) mirrored quantized store (transposed), coalesced
    if (mirror) {
        for (int i = tid; i < 8192; i += 256) {
            int trow = i >> 6;
            int tc2 = (i & 63) << 1;
            uint32_t q0 = s_tq[tc2 * 130 + trow];
            uint32_t q1 = s_tq[(tc2 + 1) * 130 + trow];
            *(uint32_t*)&Qout[(size_t)(col0 + trow) * HW + row0 + tc2] = q0 | (q1 << 16);
        }
    }
}

// ---------------- K3: combine per-tile partials -> 1/Z ----------------
__global__ __launch_bounds__(256) void rowcomb_kernel() {
    int r = blockIdx.x * 256 + threadIdx.x;
    int b = r >> 12, rr = r & (HW - 1);
    float s = 0.f;
#pragma unroll
    for (int ctile = 0; ctile < 32; ++ctile)
        s += g_sp[((size_t)b * 32 + ctile) * HW + rr];
    g_zs[r] = 1.0f / s;
}

// ---------------- branchless top-3 insert ----------------
__device__ __forceinline__ void top3_insert(float v, float& a, float& b, float& c) {
    float m1 = fminf(a, v);
    a = fmaxf(a, v);
    float m2 = fminf(b, m1);
    b = fmaxf(b, m1);
    c = fmaxf(c, m2);
}

// ---------------- decode 8 u16 -> floats ----------------
__device__ __forceinline__ void dec8(uint4 pk, float* f) {
    f[0] = (float)(pk.x & 0xFFFF); f[1] = (float)(pk.x >> 16);
    f[2] = (float)(pk.y & 0xFFFF); f[3] = (float)(pk.y >> 16);
    f[4] = (float)(pk.z & 0xFFFF); f[5] = (float)(pk.z >> 16);
    f[6] = (float)(pk.w & 0xFFFF); f[7] = (float)(pk.w >> 16);
}

// ---------------- K4: stats pass (S + top3), read-only over Q ----------------
__global__ __launch_bounds__(256) void stats_kernel(float* __restrict__ out_val) {
    __shared__ float sS[256], sa[256], sb2[256], sc2[256];
    int r = blockIdx.x, b = r >> 12, sidx = r & (HW - 1);
    int tid = threadIdx.x;
    const float* zB = g_zs + (b << 12);
    float zs = g_zs[r];
    const uint16_t* Qr = g_Q + (size_t)r * HW;

    float S = 0.f, t0 = -1.f, t1 = -1.f, t2 = -1.f;
#pragma unroll
    for (int part = 0; part < 2; ++part) {
        int t0i = (part * 256 + tid) * 8;
        uint4 pk = *(const uint4*)(Qr + t0i);
        float4 z0 = *(const float4*)&zB[t0i];
        float4 z1 = *(const float4*)&zB[t0i + 4];
        float f[8];
        dec8(pk, f);
        float u0 = exp2f(fmaf(f[0], DECK2L, BIAS2)) * z0.x;
        float u1 = exp2f(fmaf(f[1], DECK2L, BIAS2)) * z0.y;
        float u2 = exp2f(fmaf(f[2], DECK2L, BIAS2)) * z0.z;
        float u3 = exp2f(fmaf(f[3], DECK2L, BIAS2)) * z0.w;
        float u4 = exp2f(fmaf(f[4], DECK2L, BIAS2)) * z1.x;
        float u5 = exp2f(fmaf(f[5], DECK2L, BIAS2)) * z1.y;
        float u6 = exp2f(fmaf(f[6], DECK2L, BIAS2)) * z1.z;
        float u7 = exp2f(fmaf(f[7], DECK2L, BIAS2)) * z1.w;
        S += ((u0 + u1) + (u2 + u3)) + ((u4 + u5) + (u6 + u7));
        top3_insert(u0, t0, t1, t2);
        top3_insert(u1, t0, t1, t2);
        top3_insert(u2, t0, t1, t2);
        top3_insert(u3, t0, t1, t2);
        top3_insert(u4, t0, t1, t2);
        top3_insert(u5, t0, t1, t2);
        top3_insert(u6, t0, t1, t2);
        top3_insert(u7, t0, t1, t2);
    }
    sS[tid] = S; sa[tid] = t0; sb2[tid] = t1; sc2[tid] = t2;
    __syncthreads();
    for (int st = 128; st > 0; st >>= 1) {
        if (tid < st) {
            sS[tid] += sS[tid + st];
            float a0 = sa[tid + st], a1 = sb2[tid + st], a2 = sc2[tid + st];
            float b0 = sa[tid], b1 = sb2[tid], b2 = sc2[tid];
            top3_insert(a0, b0, b1, b2);
            top3_insert(a1, b0, b1, b2);
            top3_insert(a2, b0, b1, b2);
            sa[tid] = b0; sb2[tid] = b1; sc2[tid] = b2;
        }
        __syncthreads();
    }
    if (tid == 0) {
        g_S[r] = zs * sS[0];
        out_val[(b * 3 + 0) * HW + sidx] = zs * sa[0];
        out_val[(b * 3 + 1) * HW + sidx] = zs * sb2[0];
        out_val[(b * 3 + 2) * HW + sidx] = zs * sc2[0];
    }
}

// ---------------- K4b: w = z / (S + 1e-8) ----------------
__global__ __launch_bounds__(256) void srecip_kernel() {
    int i = blockIdx.x * 256 + threadIdx.x;
    g_W[i] = g_zs[i] / (g_S[i] + 1e-8f);
}

// ---------------- K5: write scaled x_soft directly (streaming stores) ----------------
__global__ __launch_bounds__(256) void write_kernel(float* __restrict__ out_soft) {
    int r = blockIdx.x, b = r >> 12;
    int tid = threadIdx.x;
    const float* wB = g_W + (b << 12);
    float zs = g_zs[r];
    const uint16_t* Qr = g_Q + (size_t)r * HW;
    float* Or = out_soft + (size_t)r * HW;
#pragma unroll
    for (int part = 0; part < 2; ++part) {
        int t0i = (part * 256 + tid) * 8;
        uint4 pk = *(const uint4*)(Qr + t0i);
        float4 w0 = *(const float4*)&wB[t0i];
        float4 w1 = *(const float4*)&wB[t0i + 4];
        float f[8];
        dec8(pk, f);
        float4 v0, v1;
        v0.x = exp2f(fmaf(f[0], DECK2L, BIAS2)) * (zs * w0.x);
        v0.y = exp2f(fmaf(f[1], DECK2L, BIAS2)) * (zs * w0.y);
        v0.z = exp2f(fmaf(f[2], DECK2L, BIAS2)) * (zs * w0.z);
        v0.w = exp2f(fmaf(f[3], DECK2L, BIAS2)) * (zs * w0.w);
        v1.x = exp2f(fmaf(f[4], DECK2L, BIAS2)) * (zs * w1.x);
        v1.y = exp2f(fmaf(f[5], DECK2L, BIAS2)) * (zs * w1.y);
        v1.z = exp2f(fmaf(f[6], DECK2L, BIAS2)) * (zs * w1.z);
        v1.w = exp2f(fmaf(f[7], DECK2L, BIAS2)) * (zs * w1.w);
        __stcs((float4*)&Or[t0i],     v0);
        __stcs((float4*)&Or[t0i + 4], v1);
    }
}

// ---------------- launch ----------------
extern "C" void kernel_launch(void* const* d_in, const int* in_sizes, int n_in,
                              void* d_out, int out_size) {
    const float* x = (const float*)d_in[0];
    const float* alpha = (const float*)d_in[1];
    float* out = (float*)d_out;
    float* out_val = out;                    // (2,3,64,64)
    float* out_soft = out + NB * 3 * HW;     // (2,4096,64,64)

    cudaFuncSetAttribute(gemm_mma_kernel,
                         cudaFuncAttributeMaxDynamicSharedMemorySize, 2 * STAGE);

    normprep_kernel<<<dim3(HW / 32, NB), 256>>>(x);
    gemm_mma_kernel<<<dim3(528, NB), 256, 2 * STAGE>>>(alpha);
    rowcomb_kernel<<<32, 256>>>();
    stats_kernel<<<NB * HW, 256>>>(out_val);
    srecip_kernel<<<32, 256>>>();
    write_kernel<<<NB * HW, 256>>>(out_soft);
}